// round 1
// baseline (speedup 1.0000x reference)
#include <cuda_runtime.h>
#include <math.h>

#define NLAYERS 4
#define DMODEL  256
#define DINNER  512
#define DSTATE  16
#define DCONV   4
#define BATCH   64
#define SEQ     900
#define TOKENS  (BATCH * SEQ)   // 57600
#define LN_EPS  1e-5f
#define LOG2E   1.4426950408889634f

// ---------------- device scratch (static, no allocation) ----------------
__device__ float g_x  [TOKENS * DMODEL];        // residual stream
__device__ float g_xz [TOKENS * 2 * DINNER];    // in_proj output (xs | res)
__device__ float g_xs [TOKENS * DINNER];        // conv+silu output
__device__ float g_ssm[TOKENS * 2 * DSTATE];    // delta(softplus) | B
__device__ float g_y  [TOKENS * DINNER];        // scan output * silu(res)
__device__ float g_o  [TOKENS * DMODEL];        // out_proj output

// ---------------- embed: x = color_embed[grid] + pos_embed ----------------
__global__ void embed_kernel(const int* __restrict__ grid,
                             const float* __restrict__ ce,
                             const float* __restrict__ pe)
{
    int idx = blockIdx.x * blockDim.x + threadIdx.x;   // TOKENS*64 float4 units
    if (idx >= TOKENS * (DMODEL / 4)) return;
    int tok = idx >> 6;
    int c4  = (idx & 63) * 4;
    int s   = tok % SEQ;
    int g   = grid[tok];
    float4 a = *(const float4*)&ce[g * DMODEL + c4];
    float4 p = *(const float4*)&pe[s * DMODEL + c4];
    float4 r; r.x = a.x + p.x; r.y = a.y + p.y; r.z = a.z + p.z; r.w = a.w + p.w;
    *(float4*)&g_x[tok * DMODEL + c4] = r;
}

// ---------------- generic fp32 tiled GEMM: C = A(MxK) @ B(KxN) + bias ----------------
#define BM 64
#define BN 64
#define BK 16
__global__ __launch_bounds__(256) void gemm_bias_kernel(
    const float* __restrict__ A, const float* __restrict__ B,
    const float* __restrict__ bias, float* __restrict__ C,
    int M, int N, int K)
{
    __shared__ float As[BM][BK + 1];
    __shared__ float Bs[BK][BN];
    int tid  = threadIdx.x;
    int row0 = blockIdx.y * BM;
    int col0 = blockIdx.x * BN;
    int tr = (tid >> 4) << 2;      // 0..60
    int tc = (tid & 15) << 2;      // 0..60
    int a_r = tid >> 2;            // 0..63
    int a_c = (tid & 3) << 2;      // 0,4,8,12
    int b_r = tid >> 4;            // 0..15
    int b_c = (tid & 15) << 2;     // 0..60

    float acc[4][4];
#pragma unroll
    for (int i = 0; i < 4; i++)
#pragma unroll
        for (int j = 0; j < 4; j++) acc[i][j] = 0.f;

    const float* Aptr = A + (row0 + a_r) * K + a_c;
    const float* Bptr = B + b_r * N + col0 + b_c;

    for (int k0 = 0; k0 < K; k0 += BK) {
        float4 av = *(const float4*)(Aptr + k0);
        As[a_r][a_c + 0] = av.x;
        As[a_r][a_c + 1] = av.y;
        As[a_r][a_c + 2] = av.z;
        As[a_r][a_c + 3] = av.w;
        *(float4*)&Bs[b_r][b_c] = *(const float4*)(Bptr + k0 * N);
        __syncthreads();
#pragma unroll
        for (int k = 0; k < BK; k++) {
            float ra0 = As[tr + 0][k];
            float ra1 = As[tr + 1][k];
            float ra2 = As[tr + 2][k];
            float ra3 = As[tr + 3][k];
            float4 rb = *(const float4*)&Bs[k][tc];
            acc[0][0] += ra0 * rb.x; acc[0][1] += ra0 * rb.y; acc[0][2] += ra0 * rb.z; acc[0][3] += ra0 * rb.w;
            acc[1][0] += ra1 * rb.x; acc[1][1] += ra1 * rb.y; acc[1][2] += ra1 * rb.z; acc[1][3] += ra1 * rb.w;
            acc[2][0] += ra2 * rb.x; acc[2][1] += ra2 * rb.y; acc[2][2] += ra2 * rb.z; acc[2][3] += ra2 * rb.w;
            acc[3][0] += ra3 * rb.x; acc[3][1] += ra3 * rb.y; acc[3][2] += ra3 * rb.z; acc[3][3] += ra3 * rb.w;
        }
        __syncthreads();
    }
    float b0 = bias[col0 + tc + 0];
    float b1 = bias[col0 + tc + 1];
    float b2 = bias[col0 + tc + 2];
    float b3 = bias[col0 + tc + 3];
#pragma unroll
    for (int i = 0; i < 4; i++) {
        float* cp = C + (row0 + tr + i) * N + col0 + tc;
        cp[0] = acc[i][0] + b0;
        cp[1] = acc[i][1] + b1;
        cp[2] = acc[i][2] + b2;
        cp[3] = acc[i][3] + b3;
    }
}

// ---------------- depthwise causal conv(4) + silu over xs half of g_xz ----------------
__global__ void conv_silu_kernel(const float* __restrict__ cw,
                                 const float* __restrict__ cb, int l)
{
    int idx = blockIdx.x * blockDim.x + threadIdx.x;   // TOKENS * 128 (c4 groups)
    if (idx >= TOKENS * (DINNER / 4)) return;
    int c4  = idx & 127;
    int tok = idx >> 7;
    int b   = tok / SEQ;
    int s   = tok % SEQ;
    int c   = c4 * 4;

    float4 w0 = *(const float4*)&cw[(l * DINNER + c + 0) * DCONV];
    float4 w1 = *(const float4*)&cw[(l * DINNER + c + 1) * DCONV];
    float4 w2 = *(const float4*)&cw[(l * DINNER + c + 2) * DCONV];
    float4 w3 = *(const float4*)&cw[(l * DINNER + c + 3) * DCONV];
    float wa[4][4] = {{w0.x,w0.y,w0.z,w0.w},{w1.x,w1.y,w1.z,w1.w},
                      {w2.x,w2.y,w2.z,w2.w},{w3.x,w3.y,w3.z,w3.w}};
    float out[4];
#pragma unroll
    for (int j = 0; j < 4; j++) out[j] = cb[l * DINNER + c + j];

#pragma unroll
    for (int k = 0; k < DCONV; k++) {
        int st = s - (DCONV - 1) + k;
        if (st >= 0) {
            float4 v = *(const float4*)&g_xz[(b * SEQ + st) * 2 * DINNER + c];
            out[0] += v.x * wa[0][k];
            out[1] += v.y * wa[1][k];
            out[2] += v.z * wa[2][k];
            out[3] += v.w * wa[3][k];
        }
    }
    float4 r;
    r.x = out[0] / (1.f + __expf(-out[0])) * 1.f; r.x = out[0] * (1.f / (1.f + __expf(-out[0])));
    r.y = out[1] * (1.f / (1.f + __expf(-out[1])));
    r.z = out[2] * (1.f / (1.f + __expf(-out[2])));
    r.w = out[3] * (1.f / (1.f + __expf(-out[3])));
    *(float4*)&g_xs[tok * DINNER + c] = r;
}

// ---------------- xproj: SSM = XS @ W(512x32) + b, softplus on first 16 ----------------
__global__ void xproj_kernel(const float* __restrict__ W,
                             const float* __restrict__ bias, int l)
{
    int gw   = (blockIdx.x * blockDim.x + threadIdx.x) >> 5;
    int lane = threadIdx.x & 31;
    if (gw >= TOKENS) return;
    const float* xs = g_xs + gw * DINNER;
    const float* Wl = W + l * DINNER * 2 * DSTATE;
    float acc = bias[l * 2 * DSTATE + lane];
#pragma unroll 4
    for (int k = 0; k < DINNER; k += 4) {
        float4 xv = *(const float4*)(xs + k);
        acc += xv.x * Wl[(k + 0) * 32 + lane];
        acc += xv.y * Wl[(k + 1) * 32 + lane];
        acc += xv.z * Wl[(k + 2) * 32 + lane];
        acc += xv.w * Wl[(k + 3) * 32 + lane];
    }
    if (lane < DSTATE)  // softplus
        acc = (acc > 20.f) ? acc : log1pf(__expf(acc));
    g_ssm[gw * 32 + lane] = acc;
}

// ---------------- selective scan, fused with * silu(res) ----------------
__global__ __launch_bounds__(128) void scan_kernel(const float* __restrict__ A_log,
                                                   const float* __restrict__ Dp, int l)
{
    int b = blockIdx.x;
    int d = blockIdx.y * 128 + threadIdx.x;

    const float* Al = A_log + (l * DINNER + d) * DSTATE;
    float a2[DSTATE];
#pragma unroll
    for (int n = 0; n < DSTATE; n++) a2[n] = -__expf(Al[n]) * LOG2E;
    float Dv = Dp[l * DINNER + d];
    float h[DSTATE];
#pragma unroll
    for (int n = 0; n < DSTATE; n++) h[n] = 0.f;

    int tok0 = b * SEQ;
    const float* ssm = g_ssm + tok0 * 32;
    const float* xsp = g_xs + tok0 * DINNER + d;
    const float* rsp = g_xz + tok0 * 2 * DINNER + DINNER + d;
    float*       yp  = g_y  + tok0 * DINNER + d;

    for (int t = 0; t < SEQ; t++) {
        float4 d0 = *(const float4*)(ssm + 0);
        float4 d1 = *(const float4*)(ssm + 4);
        float4 d2 = *(const float4*)(ssm + 8);
        float4 d3 = *(const float4*)(ssm + 12);
        float4 b0 = *(const float4*)(ssm + 16);
        float4 b1 = *(const float4*)(ssm + 20);
        float4 b2 = *(const float4*)(ssm + 24);
        float4 b3 = *(const float4*)(ssm + 28);
        float dl[DSTATE] = {d0.x,d0.y,d0.z,d0.w, d1.x,d1.y,d1.z,d1.w,
                            d2.x,d2.y,d2.z,d2.w, d3.x,d3.y,d3.z,d3.w};
        float bm[DSTATE] = {b0.x,b0.y,b0.z,b0.w, b1.x,b1.y,b1.z,b1.w,
                            b2.x,b2.y,b2.z,b2.w, b3.x,b3.y,b3.z,b3.w};
        float xv = *xsp;
        float acc = 0.f;
#pragma unroll
        for (int n = 0; n < DSTATE; n++) {
            float e = exp2f(a2[n] * dl[n]);
            h[n] = h[n] * e + xv * bm[n];
            acc += h[n] * bm[n];
        }
        float r  = *rsp;
        float sl = r * (1.f / (1.f + __expf(-r)));
        *yp = (acc + Dv * xv) * sl;

        ssm += 32; xsp += DINNER; rsp += 2 * DINNER; yp += DINNER;
    }
}

// ---------------- residual add + layernorm (warp per token) ----------------
__global__ void add_ln_kernel(const float* __restrict__ gma,
                              const float* __restrict__ bta)
{
    int gw   = (blockIdx.x * blockDim.x + threadIdx.x) >> 5;
    int lane = threadIdx.x & 31;
    if (gw >= TOKENS) return;
    float* xr = g_x + gw * DMODEL;
    const float* orow = g_o + gw * DMODEL;

    float v[8];
    float sum = 0.f;
#pragma unroll
    for (int i = 0; i < 8; i++) {
        int c = lane + i * 32;
        v[i] = xr[c] + orow[c];
        sum += v[i];
    }
#pragma unroll
    for (int o = 16; o > 0; o >>= 1) sum += __shfl_xor_sync(0xFFFFFFFF, sum, o);
    float mu = sum * (1.f / DMODEL);
    float s2 = 0.f;
#pragma unroll
    for (int i = 0; i < 8; i++) { float dd = v[i] - mu; s2 += dd * dd; }
#pragma unroll
    for (int o = 16; o > 0; o >>= 1) s2 += __shfl_xor_sync(0xFFFFFFFF, s2, o);
    float rstd = rsqrtf(s2 * (1.f / DMODEL) + LN_EPS);
#pragma unroll
    for (int i = 0; i < 8; i++) {
        int c = lane + i * 32;
        xr[c] = (v[i] - mu) * rstd * gma[c] + bta[c];
    }
}

// ---------------- heads ----------------
__global__ void heads_kernel(const float* __restrict__ c1w, const float* __restrict__ c1b,
                             const float* __restrict__ c2w, const float* __restrict__ c2b,
                             const float* __restrict__ q1w, const float* __restrict__ q1b,
                             const float* __restrict__ q2w, const float* __restrict__ q2b,
                             float* __restrict__ out)
{
    __shared__ float fin[DMODEL];
    __shared__ float hc[128], hq[128];
    int b = blockIdx.x, t = threadIdx.x;   // 128 threads
    const float* f = g_x + (b * SEQ + SEQ - 1) * DMODEL;
    fin[t] = f[t];
    fin[t + 128] = f[t + 128];
    __syncthreads();
    float a1 = c1b[t], a2 = q1b[t];
#pragma unroll 4
    for (int k = 0; k < DMODEL; k++) {
        float fv = fin[k];
        a1 += fv * c1w[k * 128 + t];
        a2 += fv * q1w[k * 128 + t];
    }
    hc[t] = fmaxf(a1, 0.f);
    hq[t] = fmaxf(a2, 0.f);
    __syncthreads();
    if (t == 0) {
        float s = c2b[0];
        for (int k = 0; k < 128; k++) s += hc[k] * c2w[k];
        out[b] = fmaxf(s, 0.f);
    }
    if (t < 10) {
        float s = q2b[t];
        for (int k = 0; k < 128; k++) s += hq[k] * q2w[k * 10 + t];
        out[BATCH + b * 10 + t] = fmaxf(s, 0.f);
    }
}

// ---------------- launch ----------------
extern "C" void kernel_launch(void* const* d_in, const int* in_sizes, int n_in,
                              void* d_out, int out_size)
{
    const int*   grid   = (const int*)  d_in[0];
    const float* ce     = (const float*)d_in[1];
    const float* pe     = (const float*)d_in[2];
    const float* in_w   = (const float*)d_in[3];
    const float* in_b   = (const float*)d_in[4];
    const float* conv_w = (const float*)d_in[5];
    const float* conv_b = (const float*)d_in[6];
    const float* xp_w   = (const float*)d_in[7];
    const float* xp_b   = (const float*)d_in[8];
    const float* A_log  = (const float*)d_in[9];
    const float* Dp     = (const float*)d_in[10];
    const float* out_w  = (const float*)d_in[11];
    const float* out_b  = (const float*)d_in[12];
    const float* ln_g   = (const float*)d_in[13];
    const float* ln_b   = (const float*)d_in[14];
    const float* c1w    = (const float*)d_in[15];
    const float* c1b    = (const float*)d_in[16];
    const float* c2w    = (const float*)d_in[17];
    const float* c2b    = (const float*)d_in[18];
    const float* q1w    = (const float*)d_in[19];
    const float* q1b    = (const float*)d_in[20];
    const float* q2w    = (const float*)d_in[21];
    const float* q2b    = (const float*)d_in[22];
    float* out = (float*)d_out;

    float *px, *pxz, *pxs, *py, *po;
    cudaGetSymbolAddress((void**)&px,  g_x);
    cudaGetSymbolAddress((void**)&pxz, g_xz);
    cudaGetSymbolAddress((void**)&pxs, g_xs);
    cudaGetSymbolAddress((void**)&py,  g_y);
    cudaGetSymbolAddress((void**)&po,  g_o);

    // embed
    {
        int n = TOKENS * (DMODEL / 4);
        embed_kernel<<<(n + 255) / 256, 256>>>(grid, ce, pe);
    }

    for (int l = 0; l < NLAYERS; l++) {
        // in_proj: (T x 256) @ (256 x 1024)
        gemm_bias_kernel<<<dim3(2 * DINNER / BN, TOKENS / BM), 256>>>(
            px, in_w + l * DMODEL * 2 * DINNER, in_b + l * 2 * DINNER, pxz,
            TOKENS, 2 * DINNER, DMODEL);

        // conv + silu
        {
            int n = TOKENS * (DINNER / 4);
            conv_silu_kernel<<<(n + 255) / 256, 256>>>(conv_w, conv_b, l);
        }

        // xproj + softplus
        xproj_kernel<<<(TOKENS * 32 + 255) / 256, 256>>>(xp_w, xp_b, l);

        // selective scan (fused * silu(res))
        scan_kernel<<<dim3(BATCH, DINNER / 128), 128>>>(A_log, Dp, l);

        // out_proj: (T x 512) @ (512 x 256)
        gemm_bias_kernel<<<dim3(DMODEL / BN, TOKENS / BM), 256>>>(
            py, out_w + l * DINNER * DMODEL, out_b + l * DMODEL, po,
            TOKENS, DMODEL, DINNER);

        // residual + layernorm
        add_ln_kernel<<<(TOKENS * 32 + 255) / 256, 256>>>(ln_g, ln_b);
    }

    heads_kernel<<<BATCH, 128>>>(c1w, c1b, c2w, c2b, q1w, q1b, q2w, q2b, out);
}

// round 2
// speedup vs baseline: 1.4072x; 1.4072x over previous
#include <cuda_runtime.h>
#include <math.h>
#include <stdint.h>

#define NLAYERS 4
#define DMODEL  256
#define DINNER  512
#define DSTATE  16
#define DCONV   4
#define BATCH   64
#define SEQ     900
#define TOKENS  (BATCH * SEQ)   // 57600
#define LN_EPS  1e-5f
#define LOG2E   1.4426950408889634f

// ---------------- device scratch (static, no allocation) ----------------
__device__ float g_x  [TOKENS * DMODEL];        // residual stream
__device__ float g_xz [TOKENS * 2 * DINNER];    // in_proj output (xs | res)
__device__ float g_xs [TOKENS * DINNER];        // conv+silu output
__device__ float g_ssm[TOKENS * 2 * DSTATE];    // delta(softplus) | B
__device__ float g_y  [TOKENS * DINNER];        // scan output * silu(res)
__device__ float g_o  [TOKENS * DMODEL];        // out_proj output

// ---------------- embed ----------------
__global__ void embed_kernel(const int* __restrict__ grid,
                             const float* __restrict__ ce,
                             const float* __restrict__ pe)
{
    int idx = blockIdx.x * blockDim.x + threadIdx.x;
    if (idx >= TOKENS * (DMODEL / 4)) return;
    int tok = idx >> 6;
    int c4  = (idx & 63) * 4;
    int s   = tok % SEQ;
    int g   = grid[tok];
    float4 a = *(const float4*)&ce[g * DMODEL + c4];
    float4 p = *(const float4*)&pe[s * DMODEL + c4];
    float4 r; r.x = a.x + p.x; r.y = a.y + p.y; r.z = a.z + p.z; r.w = a.w + p.w;
    *(float4*)&g_x[tok * DMODEL + c4] = r;
}

// ---------------- tf32 tensor-core GEMM: C = A(MxK) @ B(KxN) + bias ----------------
// Block tile 128x64, BK=16, 8 warps as 4(m) x 2(n), warp tile 32x32,
// mma.sync.m16n8k8.tf32 (2 m-tiles x 4 n-tiles per warp per k8-step).
#define GBM 128
#define GBN 64
#define GBK 16
#define A_STRIDE 20   // conflict-free: (20*r + c) % 32 distinct over r=0..7, c=0..3
#define B_STRIDE 72   // conflict-free: (72*k + c) % 32 = (8k+c)%32 distinct

__device__ __forceinline__ uint32_t f2tf32(float x) {
    uint32_t r;
    asm("cvt.rna.tf32.f32 %0, %1;" : "=r"(r) : "f"(x));
    return r;
}

__global__ __launch_bounds__(256) void gemm_tf32_kernel(
    const float* __restrict__ A, const float* __restrict__ B,
    const float* __restrict__ bias, float* __restrict__ C,
    int M, int N, int K)
{
    __shared__ uint32_t As[GBM * A_STRIDE];
    __shared__ uint32_t Bs[GBK * B_STRIDE];

    int tid  = threadIdx.x;
    int lane = tid & 31;
    int warp = tid >> 5;
    int wm   = warp >> 1;        // 0..3
    int wn   = warp & 1;         // 0..1
    int row0 = blockIdx.y * GBM;
    int col0 = blockIdx.x * GBN;

    float acc[2][4][4];
#pragma unroll
    for (int i = 0; i < 2; i++)
#pragma unroll
        for (int j = 0; j < 4; j++)
#pragma unroll
            for (int r = 0; r < 4; r++) acc[i][j][r] = 0.f;

    // global load indexing
    int a_r  = tid >> 2;          // 0..63 (two passes)
    int a_c  = (tid & 3) << 2;    // 0,4,8,12
    int b_r  = tid >> 4;          // 0..15
    int b_c  = (tid & 15) << 2;   // 0..60

    int grp = lane >> 2;          // 0..7
    int qid = lane & 3;           // 0..3

    for (int k0 = 0; k0 < K; k0 += GBK) {
        // stage A (128 x 16) with tf32 rounding
#pragma unroll
        for (int p = 0; p < 2; p++) {
            int r = a_r + p * 64;
            float4 v = *(const float4*)&A[(row0 + r) * K + k0 + a_c];
            As[r * A_STRIDE + a_c + 0] = f2tf32(v.x);
            As[r * A_STRIDE + a_c + 1] = f2tf32(v.y);
            As[r * A_STRIDE + a_c + 2] = f2tf32(v.z);
            As[r * A_STRIDE + a_c + 3] = f2tf32(v.w);
        }
        // stage B (16 x 64)
        {
            float4 v = *(const float4*)&B[(k0 + b_r) * N + col0 + b_c];
            Bs[b_r * B_STRIDE + b_c + 0] = f2tf32(v.x);
            Bs[b_r * B_STRIDE + b_c + 1] = f2tf32(v.y);
            Bs[b_r * B_STRIDE + b_c + 2] = f2tf32(v.z);
            Bs[b_r * B_STRIDE + b_c + 3] = f2tf32(v.w);
        }
        __syncthreads();

#pragma unroll
        for (int ks = 0; ks < GBK; ks += 8) {
            uint32_t af[2][4];
#pragma unroll
            for (int i = 0; i < 2; i++) {
                int r = wm * 32 + i * 16 + grp;
                af[i][0] = As[(r    ) * A_STRIDE + ks + qid    ];
                af[i][1] = As[(r + 8) * A_STRIDE + ks + qid    ];
                af[i][2] = As[(r    ) * A_STRIDE + ks + qid + 4];
                af[i][3] = As[(r + 8) * A_STRIDE + ks + qid + 4];
            }
            uint32_t bf[4][2];
#pragma unroll
            for (int j = 0; j < 4; j++) {
                int c = wn * 32 + j * 8 + grp;
                bf[j][0] = Bs[(ks + qid    ) * B_STRIDE + c];
                bf[j][1] = Bs[(ks + qid + 4) * B_STRIDE + c];
            }
#pragma unroll
            for (int i = 0; i < 2; i++)
#pragma unroll
                for (int j = 0; j < 4; j++) {
                    asm volatile(
                        "mma.sync.aligned.m16n8k8.row.col.f32.tf32.tf32.f32 "
                        "{%0,%1,%2,%3}, {%4,%5,%6,%7}, {%8,%9}, {%0,%1,%2,%3};"
                        : "+f"(acc[i][j][0]), "+f"(acc[i][j][1]),
                          "+f"(acc[i][j][2]), "+f"(acc[i][j][3])
                        : "r"(af[i][0]), "r"(af[i][1]), "r"(af[i][2]), "r"(af[i][3]),
                          "r"(bf[j][0]), "r"(bf[j][1]));
                }
        }
        __syncthreads();
    }

    // epilogue: bias + store
#pragma unroll
    for (int i = 0; i < 2; i++) {
        int rg0 = row0 + wm * 32 + i * 16 + grp;
#pragma unroll
        for (int j = 0; j < 4; j++) {
            int cg = col0 + wn * 32 + j * 8 + qid * 2;
            float b0 = bias[cg], b1 = bias[cg + 1];
            float2 v0 = make_float2(acc[i][j][0] + b0, acc[i][j][1] + b1);
            float2 v1 = make_float2(acc[i][j][2] + b0, acc[i][j][3] + b1);
            *(float2*)&C[rg0 * N + cg]       = v0;
            *(float2*)&C[(rg0 + 8) * N + cg] = v1;
        }
    }
}

// ---------------- depthwise causal conv(4) + silu ----------------
__global__ void conv_silu_kernel(const float* __restrict__ cw,
                                 const float* __restrict__ cb, int l)
{
    int idx = blockIdx.x * blockDim.x + threadIdx.x;
    if (idx >= TOKENS * (DINNER / 4)) return;
    int c4  = idx & 127;
    int tok = idx >> 7;
    int b   = tok / SEQ;
    int s   = tok % SEQ;
    int c   = c4 * 4;

    float4 w0 = *(const float4*)&cw[(l * DINNER + c + 0) * DCONV];
    float4 w1 = *(const float4*)&cw[(l * DINNER + c + 1) * DCONV];
    float4 w2 = *(const float4*)&cw[(l * DINNER + c + 2) * DCONV];
    float4 w3 = *(const float4*)&cw[(l * DINNER + c + 3) * DCONV];
    float wa[4][4] = {{w0.x,w0.y,w0.z,w0.w},{w1.x,w1.y,w1.z,w1.w},
                      {w2.x,w2.y,w2.z,w2.w},{w3.x,w3.y,w3.z,w3.w}};
    float out[4];
#pragma unroll
    for (int j = 0; j < 4; j++) out[j] = cb[l * DINNER + c + j];

#pragma unroll
    for (int k = 0; k < DCONV; k++) {
        int st = s - (DCONV - 1) + k;
        if (st >= 0) {
            float4 v = *(const float4*)&g_xz[(b * SEQ + st) * 2 * DINNER + c];
            out[0] += v.x * wa[0][k];
            out[1] += v.y * wa[1][k];
            out[2] += v.z * wa[2][k];
            out[3] += v.w * wa[3][k];
        }
    }
    float4 r;
    r.x = out[0] * (1.f / (1.f + __expf(-out[0])));
    r.y = out[1] * (1.f / (1.f + __expf(-out[1])));
    r.z = out[2] * (1.f / (1.f + __expf(-out[2])));
    r.w = out[3] * (1.f / (1.f + __expf(-out[3])));
    *(float4*)&g_xs[tok * DINNER + c] = r;
}

// ---------------- xproj: SSM = XS @ W(512x32) + b, softplus on first 16 ----------------
__global__ void xproj_kernel(const float* __restrict__ W,
                             const float* __restrict__ bias, int l)
{
    int gw   = (blockIdx.x * blockDim.x + threadIdx.x) >> 5;
    int lane = threadIdx.x & 31;
    if (gw >= TOKENS) return;
    const float* xs = g_xs + gw * DINNER;
    const float* Wl = W + l * DINNER * 2 * DSTATE;
    float acc = bias[l * 2 * DSTATE + lane];
#pragma unroll 4
    for (int k = 0; k < DINNER; k += 4) {
        float4 xv = *(const float4*)(xs + k);
        acc += xv.x * Wl[(k + 0) * 32 + lane];
        acc += xv.y * Wl[(k + 1) * 32 + lane];
        acc += xv.z * Wl[(k + 2) * 32 + lane];
        acc += xv.w * Wl[(k + 3) * 32 + lane];
    }
    if (lane < DSTATE)
        acc = (acc > 20.f) ? acc : log1pf(__expf(acc));
    g_ssm[gw * 32 + lane] = acc;
}

// ---------------- selective scan, fused with * silu(res) ----------------
__global__ __launch_bounds__(128) void scan_kernel(const float* __restrict__ A_log,
                                                   const float* __restrict__ Dp, int l)
{
    int b = blockIdx.x;
    int d = blockIdx.y * 128 + threadIdx.x;

    const float* Al = A_log + (l * DINNER + d) * DSTATE;
    float a2[DSTATE];
#pragma unroll
    for (int n = 0; n < DSTATE; n++) a2[n] = -__expf(Al[n]) * LOG2E;
    float Dv = Dp[l * DINNER + d];
    float h[DSTATE];
#pragma unroll
    for (int n = 0; n < DSTATE; n++) h[n] = 0.f;

    int tok0 = b * SEQ;
    const float* ssm = g_ssm + tok0 * 32;
    const float* xsp = g_xs + tok0 * DINNER + d;
    const float* rsp = g_xz + tok0 * 2 * DINNER + DINNER + d;
    float*       yp  = g_y  + tok0 * DINNER + d;

    for (int t = 0; t < SEQ; t++) {
        float4 d0 = *(const float4*)(ssm + 0);
        float4 d1 = *(const float4*)(ssm + 4);
        float4 d2 = *(const float4*)(ssm + 8);
        float4 d3 = *(const float4*)(ssm + 12);
        float4 b0 = *(const float4*)(ssm + 16);
        float4 b1 = *(const float4*)(ssm + 20);
        float4 b2 = *(const float4*)(ssm + 24);
        float4 b3 = *(const float4*)(ssm + 28);
        float dl[DSTATE] = {d0.x,d0.y,d0.z,d0.w, d1.x,d1.y,d1.z,d1.w,
                            d2.x,d2.y,d2.z,d2.w, d3.x,d3.y,d3.z,d3.w};
        float bm[DSTATE] = {b0.x,b0.y,b0.z,b0.w, b1.x,b1.y,b1.z,b1.w,
                            b2.x,b2.y,b2.z,b2.w, b3.x,b3.y,b3.z,b3.w};
        float xv = *xsp;
        float accv = 0.f;
#pragma unroll
        for (int n = 0; n < DSTATE; n++) {
            float e = exp2f(a2[n] * dl[n]);
            h[n] = h[n] * e + xv * bm[n];
            accv += h[n] * bm[n];
        }
        float r  = *rsp;
        float sl = r * (1.f / (1.f + __expf(-r)));
        *yp = (accv + Dv * xv) * sl;

        ssm += 32; xsp += DINNER; rsp += 2 * DINNER; yp += DINNER;
    }
}

// ---------------- residual add + layernorm ----------------
__global__ void add_ln_kernel(const float* __restrict__ gma,
                              const float* __restrict__ bta)
{
    int gw   = (blockIdx.x * blockDim.x + threadIdx.x) >> 5;
    int lane = threadIdx.x & 31;
    if (gw >= TOKENS) return;
    float* xr = g_x + gw * DMODEL;
    const float* orow = g_o + gw * DMODEL;

    float v[8];
    float sum = 0.f;
#pragma unroll
    for (int i = 0; i < 8; i++) {
        int c = lane + i * 32;
        v[i] = xr[c] + orow[c];
        sum += v[i];
    }
#pragma unroll
    for (int o = 16; o > 0; o >>= 1) sum += __shfl_xor_sync(0xFFFFFFFF, sum, o);
    float mu = sum * (1.f / DMODEL);
    float s2 = 0.f;
#pragma unroll
    for (int i = 0; i < 8; i++) { float dd = v[i] - mu; s2 += dd * dd; }
#pragma unroll
    for (int o = 16; o > 0; o >>= 1) s2 += __shfl_xor_sync(0xFFFFFFFF, s2, o);
    float rstd = rsqrtf(s2 * (1.f / DMODEL) + LN_EPS);
#pragma unroll
    for (int i = 0; i < 8; i++) {
        int c = lane + i * 32;
        xr[c] = (v[i] - mu) * rstd * gma[c] + bta[c];
    }
}

// ---------------- heads ----------------
__global__ void heads_kernel(const float* __restrict__ c1w, const float* __restrict__ c1b,
                             const float* __restrict__ c2w, const float* __restrict__ c2b,
                             const float* __restrict__ q1w, const float* __restrict__ q1b,
                             const float* __restrict__ q2w, const float* __restrict__ q2b,
                             float* __restrict__ out)
{
    __shared__ float fin[DMODEL];
    __shared__ float hc[128], hq[128];
    int b = blockIdx.x, t = threadIdx.x;
    const float* f = g_x + (b * SEQ + SEQ - 1) * DMODEL;
    fin[t] = f[t];
    fin[t + 128] = f[t + 128];
    __syncthreads();
    float a1 = c1b[t], a2 = q1b[t];
#pragma unroll 4
    for (int k = 0; k < DMODEL; k++) {
        float fv = fin[k];
        a1 += fv * c1w[k * 128 + t];
        a2 += fv * q1w[k * 128 + t];
    }
    hc[t] = fmaxf(a1, 0.f);
    hq[t] = fmaxf(a2, 0.f);
    __syncthreads();
    if (t == 0) {
        float s = c2b[0];
        for (int k = 0; k < 128; k++) s += hc[k] * c2w[k];
        out[b] = fmaxf(s, 0.f);
    }
    if (t < 10) {
        float s = q2b[t];
        for (int k = 0; k < 128; k++) s += hq[k] * q2w[k * 10 + t];
        out[BATCH + b * 10 + t] = fmaxf(s, 0.f);
    }
}

// ---------------- launch ----------------
extern "C" void kernel_launch(void* const* d_in, const int* in_sizes, int n_in,
                              void* d_out, int out_size)
{
    const int*   grid   = (const int*)  d_in[0];
    const float* ce     = (const float*)d_in[1];
    const float* pe     = (const float*)d_in[2];
    const float* in_w   = (const float*)d_in[3];
    const float* in_b   = (const float*)d_in[4];
    const float* conv_w = (const float*)d_in[5];
    const float* conv_b = (const float*)d_in[6];
    const float* xp_w   = (const float*)d_in[7];
    const float* xp_b   = (const float*)d_in[8];
    const float* A_log  = (const float*)d_in[9];
    const float* Dp     = (const float*)d_in[10];
    const float* out_w  = (const float*)d_in[11];
    const float* out_b  = (const float*)d_in[12];
    const float* ln_g   = (const float*)d_in[13];
    const float* ln_b   = (const float*)d_in[14];
    const float* c1w    = (const float*)d_in[15];
    const float* c1b    = (const float*)d_in[16];
    const float* c2w    = (const float*)d_in[17];
    const float* c2b    = (const float*)d_in[18];
    const float* q1w    = (const float*)d_in[19];
    const float* q1b    = (const float*)d_in[20];
    const float* q2w    = (const float*)d_in[21];
    const float* q2b    = (const float*)d_in[22];
    float* out = (float*)d_out;

    float *px, *pxz, *pxs, *py, *po;
    cudaGetSymbolAddress((void**)&px,  g_x);
    cudaGetSymbolAddress((void**)&pxz, g_xz);
    cudaGetSymbolAddress((void**)&pxs, g_xs);
    cudaGetSymbolAddress((void**)&py,  g_y);
    cudaGetSymbolAddress((void**)&po,  g_o);

    {
        int n = TOKENS * (DMODEL / 4);
        embed_kernel<<<(n + 255) / 256, 256>>>(grid, ce, pe);
    }

    for (int l = 0; l < NLAYERS; l++) {
        // in_proj: (T x 256) @ (256 x 1024)  -- tf32 tensor cores
        gemm_tf32_kernel<<<dim3(2 * DINNER / GBN, TOKENS / GBM), 256>>>(
            px, in_w + l * DMODEL * 2 * DINNER, in_b + l * 2 * DINNER, pxz,
            TOKENS, 2 * DINNER, DMODEL);

        {
            int n = TOKENS * (DINNER / 4);
            conv_silu_kernel<<<(n + 255) / 256, 256>>>(conv_w, conv_b, l);
        }

        xproj_kernel<<<(TOKENS * 32 + 255) / 256, 256>>>(xp_w, xp_b, l);

        scan_kernel<<<dim3(BATCH, DINNER / 128), 128>>>(A_log, Dp, l);

        // out_proj: (T x 512) @ (512 x 256)  -- tf32 tensor cores
        gemm_tf32_kernel<<<dim3(DMODEL / GBN, TOKENS / GBM), 256>>>(
            py, out_w + l * DINNER * DMODEL, out_b + l * DMODEL, po,
            TOKENS, DMODEL, DINNER);

        add_ln_kernel<<<(TOKENS * 32 + 255) / 256, 256>>>(ln_g, ln_b);
    }

    heads_kernel<<<BATCH, 128>>>(c1w, c1b, c2w, c2b, q1w, q1b, q2w, q2b, out);
}

// round 4
// speedup vs baseline: 1.5467x; 1.0992x over previous
#include <cuda_runtime.h>
#include <math.h>
#include <stdint.h>

#define NLAYERS 4
#define DMODEL  256
#define DINNER  512
#define DSTATE  16
#define DCONV   4
#define BATCH   64
#define SEQ     900
#define TOKENS  (BATCH * SEQ)   // 57600
#define LN_EPS  1e-5f
#define LOG2E   1.4426950408889634f

// ---------------- device scratch ----------------
__device__ float g_x  [TOKENS * DMODEL];
__device__ float g_xz [TOKENS * 2 * DINNER];
__device__ float g_xs [TOKENS * DINNER];
__device__ float g_ssm[TOKENS * 2 * DSTATE];
__device__ float g_y  [TOKENS * DINNER];
__device__ float g_o  [TOKENS * DMODEL];

// ---------------- embed ----------------
__global__ void embed_kernel(const int* __restrict__ grid,
                             const float* __restrict__ ce,
                             const float* __restrict__ pe)
{
    int idx = blockIdx.x * blockDim.x + threadIdx.x;
    if (idx >= TOKENS * (DMODEL / 4)) return;
    int tok = idx >> 6;
    int c4  = (idx & 63) * 4;
    int s   = tok % SEQ;
    int g   = grid[tok];
    float4 a = *(const float4*)&ce[g * DMODEL + c4];
    float4 p = *(const float4*)&pe[s * DMODEL + c4];
    float4 r; r.x = a.x + p.x; r.y = a.y + p.y; r.z = a.z + p.z; r.w = a.w + p.w;
    *(float4*)&g_x[tok * DMODEL + c4] = r;
}

// ---------------- tf32 mma.sync GEMM, 128x128 tile, double-buffered ----------------
// C(MxN) = A(MxK) @ B(KxN) + bias.  8 warps as 2(m) x 4(n), warp tile 64x32.
#define GBM 128
#define GBN 128
#define GBK 16
#define ASTRIDE 20    // (20*grp + qid) % 32 distinct over grp 0..7, qid 0..3
#define BSTRIDE 136   // (136*k + c) % 32 = (8k + c) % 32 distinct

__device__ __forceinline__ uint32_t f2tf32(float x) {
    uint32_t r;
    asm("cvt.rna.tf32.f32 %0, %1;" : "=r"(r) : "f"(x));
    return r;
}

__global__ __launch_bounds__(256) void gemm_tf32_kernel(
    const float* __restrict__ A, const float* __restrict__ B,
    const float* __restrict__ bias, float* __restrict__ C,
    int M, int N, int K)
{
    __shared__ uint32_t As[2][GBM * ASTRIDE];   // 2*128*20*4 = 20480 B
    __shared__ uint32_t Bs[2][GBK * BSTRIDE];   // 2*16*136*4 = 17408 B

    int tid  = threadIdx.x;
    int lane = tid & 31;
    int warp = tid >> 5;
    int wm   = warp >> 2;        // 0..1
    int wn   = warp & 3;         // 0..3
    int row0 = blockIdx.y * GBM;
    int col0 = blockIdx.x * GBN;

    float acc[4][4][4];
#pragma unroll
    for (int i = 0; i < 4; i++)
#pragma unroll
        for (int j = 0; j < 4; j++)
#pragma unroll
            for (int r = 0; r < 4; r++) acc[i][j][r] = 0.f;

    // global load indexing
    int a_r = tid >> 2;            // 0..63 (rows a_r, a_r+64)
    int a_c = (tid & 3) << 2;      // 0,4,8,12
    int b_r = tid >> 5;            // 0..7 (rows b_r, b_r+8)
    int b_c = (tid & 31) << 2;     // 0..124

    int grp = lane >> 2;           // 0..7
    int qid = lane & 3;            // 0..3

    const float* Ap0 = A + (size_t)(row0 + a_r) * K + a_c;
    const float* Ap1 = A + (size_t)(row0 + a_r + 64) * K + a_c;
    const float* Bp0 = B + (size_t)b_r * N + col0 + b_c;
    const float* Bp1 = B + (size_t)(b_r + 8) * N + col0 + b_c;

    int NC = K / GBK;

    // prologue: load + store chunk 0
    float4 av0 = *(const float4*)(Ap0);
    float4 av1 = *(const float4*)(Ap1);
    float4 bv0 = *(const float4*)(Bp0);
    float4 bv1 = *(const float4*)(Bp1);
    {
        uint32_t* asb = &As[0][0];
        asb[a_r * ASTRIDE + a_c + 0] = f2tf32(av0.x);
        asb[a_r * ASTRIDE + a_c + 1] = f2tf32(av0.y);
        asb[a_r * ASTRIDE + a_c + 2] = f2tf32(av0.z);
        asb[a_r * ASTRIDE + a_c + 3] = f2tf32(av0.w);
        asb[(a_r + 64) * ASTRIDE + a_c + 0] = f2tf32(av1.x);
        asb[(a_r + 64) * ASTRIDE + a_c + 1] = f2tf32(av1.y);
        asb[(a_r + 64) * ASTRIDE + a_c + 2] = f2tf32(av1.z);
        asb[(a_r + 64) * ASTRIDE + a_c + 3] = f2tf32(av1.w);
        uint32_t* bsb = &Bs[0][0];
        bsb[b_r * BSTRIDE + b_c + 0] = f2tf32(bv0.x);
        bsb[b_r * BSTRIDE + b_c + 1] = f2tf32(bv0.y);
        bsb[b_r * BSTRIDE + b_c + 2] = f2tf32(bv0.z);
        bsb[b_r * BSTRIDE + b_c + 3] = f2tf32(bv0.w);
        bsb[(b_r + 8) * BSTRIDE + b_c + 0] = f2tf32(bv1.x);
        bsb[(b_r + 8) * BSTRIDE + b_c + 1] = f2tf32(bv1.y);
        bsb[(b_r + 8) * BSTRIDE + b_c + 2] = f2tf32(bv1.z);
        bsb[(b_r + 8) * BSTRIDE + b_c + 3] = f2tf32(bv1.w);
    }
    __syncthreads();

    for (int c = 0; c < NC; c++) {
        int buf = c & 1;
        // prefetch next chunk into registers
        if (c + 1 < NC) {
            int k0 = (c + 1) * GBK;
            av0 = *(const float4*)(Ap0 + k0);
            av1 = *(const float4*)(Ap1 + k0);
            bv0 = *(const float4*)(Bp0 + (size_t)k0 * N);
            bv1 = *(const float4*)(Bp1 + (size_t)k0 * N);
        }
        // compute from buf
        const uint32_t* asb = &As[buf][0];
        const uint32_t* bsb = &Bs[buf][0];
#pragma unroll
        for (int ks = 0; ks < GBK; ks += 8) {
            uint32_t af[4][4];
#pragma unroll
            for (int i = 0; i < 4; i++) {
                int r = wm * 64 + i * 16 + grp;
                af[i][0] = asb[(r    ) * ASTRIDE + ks + qid    ];
                af[i][1] = asb[(r + 8) * ASTRIDE + ks + qid    ];
                af[i][2] = asb[(r    ) * ASTRIDE + ks + qid + 4];
                af[i][3] = asb[(r + 8) * ASTRIDE + ks + qid + 4];
            }
            uint32_t bf[4][2];
#pragma unroll
            for (int j = 0; j < 4; j++) {
                int cc = wn * 32 + j * 8 + grp;
                bf[j][0] = bsb[(ks + qid    ) * BSTRIDE + cc];
                bf[j][1] = bsb[(ks + qid + 4) * BSTRIDE + cc];
            }
#pragma unroll
            for (int i = 0; i < 4; i++)
#pragma unroll
                for (int j = 0; j < 4; j++) {
                    asm volatile(
                        "mma.sync.aligned.m16n8k8.row.col.f32.tf32.tf32.f32 "
                        "{%0,%1,%2,%3}, {%4,%5,%6,%7}, {%8,%9}, {%0,%1,%2,%3};"
                        : "+f"(acc[i][j][0]), "+f"(acc[i][j][1]),
                          "+f"(acc[i][j][2]), "+f"(acc[i][j][3])
                        : "r"(af[i][0]), "r"(af[i][1]), "r"(af[i][2]), "r"(af[i][3]),
                          "r"(bf[j][0]), "r"(bf[j][1]));
                }
        }
        // store prefetched chunk into the other buffer
        if (c + 1 < NC) {
            int nb = buf ^ 1;
            uint32_t* asw = &As[nb][0];
            asw[a_r * ASTRIDE + a_c + 0] = f2tf32(av0.x);
            asw[a_r * ASTRIDE + a_c + 1] = f2tf32(av0.y);
            asw[a_r * ASTRIDE + a_c + 2] = f2tf32(av0.z);
            asw[a_r * ASTRIDE + a_c + 3] = f2tf32(av0.w);
            asw[(a_r + 64) * ASTRIDE + a_c + 0] = f2tf32(av1.x);
            asw[(a_r + 64) * ASTRIDE + a_c + 1] = f2tf32(av1.y);
            asw[(a_r + 64) * ASTRIDE + a_c + 2] = f2tf32(av1.z);
            asw[(a_r + 64) * ASTRIDE + a_c + 3] = f2tf32(av1.w);
            uint32_t* bsw = &Bs[nb][0];
            bsw[b_r * BSTRIDE + b_c + 0] = f2tf32(bv0.x);
            bsw[b_r * BSTRIDE + b_c + 1] = f2tf32(bv0.y);
            bsw[b_r * BSTRIDE + b_c + 2] = f2tf32(bv0.z);
            bsw[b_r * BSTRIDE + b_c + 3] = f2tf32(bv0.w);
            bsw[(b_r + 8) * BSTRIDE + b_c + 0] = f2tf32(bv1.x);
            bsw[(b_r + 8) * BSTRIDE + b_c + 1] = f2tf32(bv1.y);
            bsw[(b_r + 8) * BSTRIDE + b_c + 2] = f2tf32(bv1.z);
            bsw[(b_r + 8) * BSTRIDE + b_c + 3] = f2tf32(bv1.w);
        }
        __syncthreads();
    }

    // epilogue: bias + store
#pragma unroll
    for (int i = 0; i < 4; i++) {
        int rg0 = row0 + wm * 64 + i * 16 + grp;
#pragma unroll
        for (int j = 0; j < 4; j++) {
            int cg = col0 + wn * 32 + j * 8 + qid * 2;
            float b0 = bias[cg], b1 = bias[cg + 1];
            float2 v0 = make_float2(acc[i][j][0] + b0, acc[i][j][1] + b1);
            float2 v1 = make_float2(acc[i][j][2] + b0, acc[i][j][3] + b1);
            *(float2*)&C[(size_t)rg0 * N + cg]       = v0;
            *(float2*)&C[(size_t)(rg0 + 8) * N + cg] = v1;
        }
    }
}

// ---------------- depthwise causal conv(4) + silu ----------------
__global__ void conv_silu_kernel(const float* __restrict__ cw,
                                 const float* __restrict__ cb, int l)
{
    int idx = blockIdx.x * blockDim.x + threadIdx.x;
    if (idx >= TOKENS * (DINNER / 4)) return;
    int c4  = idx & 127;
    int tok = idx >> 7;
    int b   = tok / SEQ;
    int s   = tok % SEQ;
    int c   = c4 * 4;

    float4 w0 = *(const float4*)&cw[(l * DINNER + c + 0) * DCONV];
    float4 w1 = *(const float4*)&cw[(l * DINNER + c + 1) * DCONV];
    float4 w2 = *(const float4*)&cw[(l * DINNER + c + 2) * DCONV];
    float4 w3 = *(const float4*)&cw[(l * DINNER + c + 3) * DCONV];
    float wa[4][4] = {{w0.x,w0.y,w0.z,w0.w},{w1.x,w1.y,w1.z,w1.w},
                      {w2.x,w2.y,w2.z,w2.w},{w3.x,w3.y,w3.z,w3.w}};
    float out[4];
#pragma unroll
    for (int j = 0; j < 4; j++) out[j] = cb[l * DINNER + c + j];

#pragma unroll
    for (int k = 0; k < DCONV; k++) {
        int st = s - (DCONV - 1) + k;
        if (st >= 0) {
            float4 v = *(const float4*)&g_xz[(size_t)(b * SEQ + st) * 2 * DINNER + c];
            out[0] += v.x * wa[0][k];
            out[1] += v.y * wa[1][k];
            out[2] += v.z * wa[2][k];
            out[3] += v.w * wa[3][k];
        }
    }
    float4 r;
    r.x = out[0] * (1.f / (1.f + __expf(-out[0])));
    r.y = out[1] * (1.f / (1.f + __expf(-out[1])));
    r.z = out[2] * (1.f / (1.f + __expf(-out[2])));
    r.w = out[3] * (1.f / (1.f + __expf(-out[3])));
    *(float4*)&g_xs[(size_t)tok * DINNER + c] = r;
}

// ---------------- xproj: W staged in SMEM, 4 tokens per inner loop ----------------
// SSM = XS(Tx512) @ W(512x32) + b, softplus on first 16 columns.
__global__ __launch_bounds__(256) void xproj_kernel(const float* __restrict__ W,
                                                    const float* __restrict__ bias, int l)
{
    extern __shared__ float Ws[];   // 512*32 floats = 64 KB
    int tid  = threadIdx.x;
    int lane = tid & 31;
    int warp = tid >> 5;

    const float* Wl = W + (size_t)l * DINNER * 32;
#pragma unroll
    for (int i = 0; i < 16; i++) {
        int li = (i * 256 + tid) * 4;
        *(float4*)&Ws[li] = *(const float4*)&Wl[li];
    }
    __syncthreads();

    float bv = bias[l * 32 + lane];
    int base = blockIdx.x * 128 + warp * 16;

#pragma unroll
    for (int g = 0; g < 4; g++) {
        int tok = base + g * 4;
        const float* x0 = g_xs + (size_t)(tok + 0) * DINNER;
        const float* x1 = g_xs + (size_t)(tok + 1) * DINNER;
        const float* x2 = g_xs + (size_t)(tok + 2) * DINNER;
        const float* x3 = g_xs + (size_t)(tok + 3) * DINNER;
        float a0 = bv, a1 = bv, a2 = bv, a3 = bv;
#pragma unroll 4
        for (int k = 0; k < DINNER; k += 4) {
            float w0 = Ws[(k + 0) * 32 + lane];
            float w1 = Ws[(k + 1) * 32 + lane];
            float w2 = Ws[(k + 2) * 32 + lane];
            float w3 = Ws[(k + 3) * 32 + lane];
            float4 v0 = *(const float4*)(x0 + k);
            float4 v1 = *(const float4*)(x1 + k);
            float4 v2 = *(const float4*)(x2 + k);
            float4 v3 = *(const float4*)(x3 + k);
            a0 += v0.x * w0 + v0.y * w1 + v0.z * w2 + v0.w * w3;
            a1 += v1.x * w0 + v1.y * w1 + v1.z * w2 + v1.w * w3;
            a2 += v2.x * w0 + v2.y * w1 + v2.z * w2 + v2.w * w3;
            a3 += v3.x * w0 + v3.y * w1 + v3.z * w2 + v3.w * w3;
        }
        if (lane < DSTATE) {
            a0 = (a0 > 20.f) ? a0 : log1pf(__expf(a0));
            a1 = (a1 > 20.f) ? a1 : log1pf(__expf(a1));
            a2 = (a2 > 20.f) ? a2 : log1pf(__expf(a2));
            a3 = (a3 > 20.f) ? a3 : log1pf(__expf(a3));
        }
        g_ssm[(size_t)(tok + 0) * 32 + lane] = a0;
        g_ssm[(size_t)(tok + 1) * 32 + lane] = a1;
        g_ssm[(size_t)(tok + 2) * 32 + lane] = a2;
        g_ssm[(size_t)(tok + 3) * 32 + lane] = a3;
    }
}

// ---------------- selective scan, fused with * silu(res) ----------------
__global__ __launch_bounds__(128) void scan_kernel(const float* __restrict__ A_log,
                                                   const float* __restrict__ Dp, int l)
{
    int b = blockIdx.x;
    int d = blockIdx.y * 128 + threadIdx.x;

    const float* Al = A_log + (l * DINNER + d) * DSTATE;
    float a2[DSTATE];
#pragma unroll
    for (int n = 0; n < DSTATE; n++) a2[n] = -__expf(Al[n]) * LOG2E;
    float Dv = Dp[l * DINNER + d];
    float h[DSTATE];
#pragma unroll
    for (int n = 0; n < DSTATE; n++) h[n] = 0.f;

    int tok0 = b * SEQ;
    const float* ssm = g_ssm + (size_t)tok0 * 32;
    const float* xsp = g_xs + (size_t)tok0 * DINNER + d;
    const float* rsp = g_xz + (size_t)tok0 * 2 * DINNER + DINNER + d;
    float*       yp  = g_y  + (size_t)tok0 * DINNER + d;

    for (int t = 0; t < SEQ; t++) {
        float4 d0 = *(const float4*)(ssm + 0);
        float4 d1 = *(const float4*)(ssm + 4);
        float4 d2 = *(const float4*)(ssm + 8);
        float4 d3 = *(const float4*)(ssm + 12);
        float4 b0 = *(const float4*)(ssm + 16);
        float4 b1 = *(const float4*)(ssm + 20);
        float4 b2 = *(const float4*)(ssm + 24);
        float4 b3 = *(const float4*)(ssm + 28);
        float dl[DSTATE] = {d0.x,d0.y,d0.z,d0.w, d1.x,d1.y,d1.z,d1.w,
                            d2.x,d2.y,d2.z,d2.w, d3.x,d3.y,d3.z,d3.w};
        float bm[DSTATE] = {b0.x,b0.y,b0.z,b0.w, b1.x,b1.y,b1.z,b1.w,
                            b2.x,b2.y,b2.z,b2.w, b3.x,b3.y,b3.z,b3.w};
        float xv = *xsp;
        float accv = 0.f;
#pragma unroll
        for (int n = 0; n < DSTATE; n++) {
            float e = exp2f(a2[n] * dl[n]);
            h[n] = h[n] * e + xv * bm[n];
            accv += h[n] * bm[n];
        }
        float r  = *rsp;
        float sl = r * (1.f / (1.f + __expf(-r)));
        *yp = (accv + Dv * xv) * sl;

        ssm += 32; xsp += DINNER; rsp += 2 * DINNER; yp += DINNER;
    }
}

// ---------------- residual add + layernorm ----------------
__global__ void add_ln_kernel(const float* __restrict__ gma,
                              const float* __restrict__ bta)
{
    int gw   = (blockIdx.x * blockDim.x + threadIdx.x) >> 5;
    int lane = threadIdx.x & 31;
    if (gw >= TOKENS) return;
    float* xr = g_x + (size_t)gw * DMODEL;
    const float* orow = g_o + (size_t)gw * DMODEL;

    float v[8];
    float sum = 0.f;
#pragma unroll
    for (int i = 0; i < 8; i++) {
        int c = lane + i * 32;
        v[i] = xr[c] + orow[c];
        sum += v[i];
    }
#pragma unroll
    for (int o = 16; o > 0; o >>= 1) sum += __shfl_xor_sync(0xFFFFFFFF, sum, o);
    float mu = sum * (1.f / DMODEL);
    float s2 = 0.f;
#pragma unroll
    for (int i = 0; i < 8; i++) { float dd = v[i] - mu; s2 += dd * dd; }
#pragma unroll
    for (int o = 16; o > 0; o >>= 1) s2 += __shfl_xor_sync(0xFFFFFFFF, s2, o);
    float rstd = rsqrtf(s2 * (1.f / DMODEL) + LN_EPS);
#pragma unroll
    for (int i = 0; i < 8; i++) {
        int c = lane + i * 32;
        xr[c] = (v[i] - mu) * rstd * gma[c] + bta[c];
    }
}

// ---------------- heads ----------------
__global__ void heads_kernel(const float* __restrict__ c1w, const float* __restrict__ c1b,
                             const float* __restrict__ c2w, const float* __restrict__ c2b,
                             const float* __restrict__ q1w, const float* __restrict__ q1b,
                             const float* __restrict__ q2w, const float* __restrict__ q2b,
                             float* __restrict__ out)
{
    __shared__ float fin[DMODEL];
    __shared__ float hc[128], hq[128];
    int b = blockIdx.x, t = threadIdx.x;
    const float* f = g_x + (size_t)(b * SEQ + SEQ - 1) * DMODEL;
    fin[t] = f[t];
    fin[t + 128] = f[t + 128];
    __syncthreads();
    float a1 = c1b[t], a2 = q1b[t];
#pragma unroll 4
    for (int k = 0; k < DMODEL; k++) {
        float fv = fin[k];
        a1 += fv * c1w[k * 128 + t];
        a2 += fv * q1w[k * 128 + t];
    }
    hc[t] = fmaxf(a1, 0.f);
    hq[t] = fmaxf(a2, 0.f);
    __syncthreads();
    if (t == 0) {
        float s = c2b[0];
        for (int k = 0; k < 128; k++) s += hc[k] * c2w[k];
        out[b] = fmaxf(s, 0.f);
    }
    if (t < 10) {
        float s = q2b[t];
        for (int k = 0; k < 128; k++) s += hq[k] * q2w[k * 10 + t];
        out[BATCH + b * 10 + t] = fmaxf(s, 0.f);
    }
}

// ---------------- launch ----------------
extern "C" void kernel_launch(void* const* d_in, const int* in_sizes, int n_in,
                              void* d_out, int out_size)
{
    const int*   grid   = (const int*)  d_in[0];
    const float* ce     = (const float*)d_in[1];
    const float* pe     = (const float*)d_in[2];
    const float* in_w   = (const float*)d_in[3];
    const float* in_b   = (const float*)d_in[4];
    const float* conv_w = (const float*)d_in[5];
    const float* conv_b = (const float*)d_in[6];
    const float* xp_w   = (const float*)d_in[7];
    const float* xp_b   = (const float*)d_in[8];
    const float* A_log  = (const float*)d_in[9];
    const float* Dp     = (const float*)d_in[10];
    const float* out_w  = (const float*)d_in[11];
    const float* out_b  = (const float*)d_in[12];
    const float* ln_g   = (const float*)d_in[13];
    const float* ln_b   = (const float*)d_in[14];
    const float* c1w    = (const float*)d_in[15];
    const float* c1b    = (const float*)d_in[16];
    const float* c2w    = (const float*)d_in[17];
    const float* c2b    = (const float*)d_in[18];
    const float* q1w    = (const float*)d_in[19];
    const float* q1b    = (const float*)d_in[20];
    const float* q2w    = (const float*)d_in[21];
    const float* q2b    = (const float*)d_in[22];
    float* out = (float*)d_out;

    float *px, *pxz, *pxs, *py, *po;
    cudaGetSymbolAddress((void**)&px,  g_x);
    cudaGetSymbolAddress((void**)&pxz, g_xz);
    cudaGetSymbolAddress((void**)&pxs, g_xs);
    cudaGetSymbolAddress((void**)&py,  g_y);
    cudaGetSymbolAddress((void**)&po,  g_o);

    cudaFuncSetAttribute(xproj_kernel, cudaFuncAttributeMaxDynamicSharedMemorySize,
                         DINNER * 32 * (int)sizeof(float));

    {
        int n = TOKENS * (DMODEL / 4);
        embed_kernel<<<(n + 255) / 256, 256>>>(grid, ce, pe);
    }

    for (int l = 0; l < NLAYERS; l++) {
        // in_proj: (T x 256) @ (256 x 1024)
        gemm_tf32_kernel<<<dim3(2 * DINNER / GBN, TOKENS / GBM), 256>>>(
            px, in_w + (size_t)l * DMODEL * 2 * DINNER, in_b + l * 2 * DINNER, pxz,
            TOKENS, 2 * DINNER, DMODEL);

        {
            int n = TOKENS * (DINNER / 4);
            conv_silu_kernel<<<(n + 255) / 256, 256>>>(conv_w, conv_b, l);
        }

        // xproj (W in SMEM): (T x 512) @ (512 x 32), softplus fused
        xproj_kernel<<<TOKENS / 128, 256, DINNER * 32 * sizeof(float)>>>(xp_w, xp_b, l);

        scan_kernel<<<dim3(BATCH, DINNER / 128), 128>>>(A_log, Dp, l);

        // out_proj: (T x 512) @ (512 x 256)
        gemm_tf32_kernel<<<dim3(DMODEL / GBN, TOKENS / GBM), 256>>>(
            py, out_w + (size_t)l * DINNER * DMODEL, out_b + l * DMODEL, po,
            TOKENS, DMODEL, DINNER);

        add_ln_kernel<<<(TOKENS * 32 + 255) / 256, 256>>>(ln_g, ln_b);
    }

    heads_kernel<<<BATCH, 128>>>(c1w, c1b, c2w, c2b, q1w, q1b, q2w, q2b, out);
}

// round 5
// speedup vs baseline: 1.6471x; 1.0649x over previous
#include <cuda_runtime.h>
#include <math.h>
#include <stdint.h>

#define NLAYERS 4
#define DMODEL  256
#define DINNER  512
#define DSTATE  16
#define DCONV   4
#define BATCH   64
#define SEQ     900
#define TOKENS  (BATCH * SEQ)   // 57600
#define LN_EPS  1e-5f
#define LOG2E   1.4426950408889634f

// ---------------- device scratch ----------------
__device__ float g_x  [TOKENS * DMODEL];
__device__ float g_xz [TOKENS * 2 * DINNER];
__device__ float g_xs [TOKENS * DINNER];
__device__ float g_ssm[TOKENS * 2 * DSTATE];
__device__ float g_y  [TOKENS * DINNER];
__device__ float g_o  [TOKENS * DMODEL];
// pre-transposed bf16x2-packed weights, K-major: [N][K/2] u32 words
__device__ uint32_t g_wbi[NLAYERS * 2 * DINNER * (DMODEL / 2)];  // in_w^T
__device__ uint32_t g_wbo[NLAYERS * DMODEL * (DINNER / 2)];      // out_w^T

__device__ __forceinline__ uint32_t packbf(float lo, float hi) {
    uint32_t r;
    asm("cvt.rn.bf16x2.f32 %0, %1, %2;" : "=r"(r) : "f"(hi), "f"(lo));
    return r;
}

// ---------------- weight convert+transpose: wt[n][k/2] = pack(w[2k2][n], w[2k2+1][n]) ----------------
__global__ void convert_w_kernel(const float* __restrict__ w, uint32_t* __restrict__ wt,
                                 int K, int N)
{
    int idx = blockIdx.x * blockDim.x + threadIdx.x;
    if (idx >= N * (K / 2)) return;
    int n  = idx % N;          // coalesced reads along n
    int k2 = idx / N;
    float lo = w[(size_t)(2 * k2) * N + n];
    float hi = w[(size_t)(2 * k2 + 1) * N + n];
    wt[(size_t)n * (K / 2) + k2] = packbf(lo, hi);
}

// ---------------- embed ----------------
__global__ void embed_kernel(const int* __restrict__ grid,
                             const float* __restrict__ ce,
                             const float* __restrict__ pe)
{
    int idx = blockIdx.x * blockDim.x + threadIdx.x;
    if (idx >= TOKENS * (DMODEL / 4)) return;
    int tok = idx >> 6;
    int c4  = (idx & 63) * 4;
    int s   = tok % SEQ;
    int g   = grid[tok];
    float4 a = *(const float4*)&ce[g * DMODEL + c4];
    float4 p = *(const float4*)&pe[s * DMODEL + c4];
    float4 r; r.x = a.x + p.x; r.y = a.y + p.y; r.z = a.z + p.z; r.w = a.w + p.w;
    *(float4*)&g_x[tok * DMODEL + c4] = r;
}

// ---------------- bf16 mma.sync GEMM, 128x128 tile, GBK=32, double-buffered ----------------
// C(MxN) = A(MxK) @ W^T + bias, A fp32 row-major, W bf16x2-packed K-major [N][K/2].
// 8 warps as 2(m) x 4(n), warp tile 64x32, m16n8k16.bf16.
#define GBM 128
#define GBN 128
#define GBK 32
#define KW  (GBK / 2)    // 16 u32 words per row-chunk
#define AS  20           // word stride (16 + 4 pad): banks (20*grp+qid)%32 distinct
#define BS  20

__global__ __launch_bounds__(256, 2) void gemm_bf16_kernel(
    const float* __restrict__ A, const uint32_t* __restrict__ Bw,
    const float* __restrict__ bias, float* __restrict__ C,
    int M, int N, int K)
{
    __shared__ uint32_t As_[2][GBM * AS];   // 2*128*20*4 = 20480 B
    __shared__ uint32_t Bs_[2][GBN * BS];   // 20480 B

    int tid  = threadIdx.x;
    int lane = tid & 31;
    int warp = tid >> 5;
    int wm   = warp >> 2;          // 0..1
    int wn   = warp & 3;           // 0..3
    int row0 = blockIdx.y * GBM;
    int col0 = blockIdx.x * GBN;
    int grp  = lane >> 2;          // 0..7
    int qid  = lane & 3;           // 0..3

    float acc[4][4][4];
#pragma unroll
    for (int i = 0; i < 4; i++)
#pragma unroll
        for (int j = 0; j < 4; j++)
#pragma unroll
            for (int r = 0; r < 4; r++) acc[i][j][r] = 0.f;

    // staging indices
    int a_r = tid >> 2;            // 0..63 (rows a_r, a_r+64)
    int a_c = (tid & 3) << 3;      // float offset 0,8,16,24
    int a_w = (tid & 3) << 2;      // word offset 0,4,8,12
    int b_n = tid >> 1;            // 0..127
    int b_w = (tid & 1) << 3;      // word offset 0 or 8

    const float*    Ap0 = A + (size_t)(row0 + a_r) * K + a_c;
    const float*    Ap1 = A + (size_t)(row0 + a_r + 64) * K + a_c;
    const uint32_t* Bp  = Bw + (size_t)(col0 + b_n) * (K / 2) + b_w;

    int NC = K / GBK;

    // prologue
    float4 av0 = *(const float4*)(Ap0);
    float4 av1 = *(const float4*)(Ap0 + 4);
    float4 av2 = *(const float4*)(Ap1);
    float4 av3 = *(const float4*)(Ap1 + 4);
    uint4  u0  = *(const uint4*)(Bp);
    uint4  u1  = *(const uint4*)(Bp + 4);
    {
        uint32_t* as = &As_[0][0];
        as[a_r * AS + a_w + 0] = packbf(av0.x, av0.y);
        as[a_r * AS + a_w + 1] = packbf(av0.z, av0.w);
        as[a_r * AS + a_w + 2] = packbf(av1.x, av1.y);
        as[a_r * AS + a_w + 3] = packbf(av1.z, av1.w);
        as[(a_r + 64) * AS + a_w + 0] = packbf(av2.x, av2.y);
        as[(a_r + 64) * AS + a_w + 1] = packbf(av2.z, av2.w);
        as[(a_r + 64) * AS + a_w + 2] = packbf(av3.x, av3.y);
        as[(a_r + 64) * AS + a_w + 3] = packbf(av3.z, av3.w);
        uint32_t* bs = &Bs_[0][0];
        bs[b_n * BS + b_w + 0] = u0.x;
        bs[b_n * BS + b_w + 1] = u0.y;
        bs[b_n * BS + b_w + 2] = u0.z;
        bs[b_n * BS + b_w + 3] = u0.w;
        bs[b_n * BS + b_w + 4] = u1.x;
        bs[b_n * BS + b_w + 5] = u1.y;
        bs[b_n * BS + b_w + 6] = u1.z;
        bs[b_n * BS + b_w + 7] = u1.w;
    }
    __syncthreads();

    for (int c = 0; c < NC; c++) {
        int buf = c & 1;
        if (c + 1 < NC) {
            int k0 = (c + 1) * GBK;
            av0 = *(const float4*)(Ap0 + k0);
            av1 = *(const float4*)(Ap0 + k0 + 4);
            av2 = *(const float4*)(Ap1 + k0);
            av3 = *(const float4*)(Ap1 + k0 + 4);
            u0  = *(const uint4*)(Bp + k0 / 2);
            u1  = *(const uint4*)(Bp + k0 / 2 + 4);
        }
        const uint32_t* as = &As_[buf][0];
        const uint32_t* bs = &Bs_[buf][0];
#pragma unroll
        for (int ks = 0; ks < 2; ks++) {
            int wof = ks * 8;
            uint32_t af[4][4];
#pragma unroll
            for (int i = 0; i < 4; i++) {
                int r = wm * 64 + i * 16 + grp;
                af[i][0] = as[(r    ) * AS + wof + qid    ];
                af[i][1] = as[(r + 8) * AS + wof + qid    ];
                af[i][2] = as[(r    ) * AS + wof + qid + 4];
                af[i][3] = as[(r + 8) * AS + wof + qid + 4];
            }
            uint32_t bf_[4][2];
#pragma unroll
            for (int j = 0; j < 4; j++) {
                int cc = wn * 32 + j * 8 + grp;
                bf_[j][0] = bs[cc * BS + wof + qid    ];
                bf_[j][1] = bs[cc * BS + wof + qid + 4];
            }
#pragma unroll
            for (int i = 0; i < 4; i++)
#pragma unroll
                for (int j = 0; j < 4; j++) {
                    asm volatile(
                        "mma.sync.aligned.m16n8k16.row.col.f32.bf16.bf16.f32 "
                        "{%0,%1,%2,%3}, {%4,%5,%6,%7}, {%8,%9}, {%0,%1,%2,%3};"
                        : "+f"(acc[i][j][0]), "+f"(acc[i][j][1]),
                          "+f"(acc[i][j][2]), "+f"(acc[i][j][3])
                        : "r"(af[i][0]), "r"(af[i][1]), "r"(af[i][2]), "r"(af[i][3]),
                          "r"(bf_[j][0]), "r"(bf_[j][1]));
                }
        }
        if (c + 1 < NC) {
            int nb = buf ^ 1;
            uint32_t* asw = &As_[nb][0];
            asw[a_r * AS + a_w + 0] = packbf(av0.x, av0.y);
            asw[a_r * AS + a_w + 1] = packbf(av0.z, av0.w);
            asw[a_r * AS + a_w + 2] = packbf(av1.x, av1.y);
            asw[a_r * AS + a_w + 3] = packbf(av1.z, av1.w);
            asw[(a_r + 64) * AS + a_w + 0] = packbf(av2.x, av2.y);
            asw[(a_r + 64) * AS + a_w + 1] = packbf(av2.z, av2.w);
            asw[(a_r + 64) * AS + a_w + 2] = packbf(av3.x, av3.y);
            asw[(a_r + 64) * AS + a_w + 3] = packbf(av3.z, av3.w);
            uint32_t* bsw = &Bs_[nb][0];
            bsw[b_n * BS + b_w + 0] = u0.x;
            bsw[b_n * BS + b_w + 1] = u0.y;
            bsw[b_n * BS + b_w + 2] = u0.z;
            bsw[b_n * BS + b_w + 3] = u0.w;
            bsw[b_n * BS + b_w + 4] = u1.x;
            bsw[b_n * BS + b_w + 5] = u1.y;
            bsw[b_n * BS + b_w + 6] = u1.z;
            bsw[b_n * BS + b_w + 7] = u1.w;
        }
        __syncthreads();
    }

    // epilogue: bias + fp32 store
#pragma unroll
    for (int i = 0; i < 4; i++) {
        int rg0 = row0 + wm * 64 + i * 16 + grp;
#pragma unroll
        for (int j = 0; j < 4; j++) {
            int cg = col0 + wn * 32 + j * 8 + qid * 2;
            float b0 = bias[cg], b1 = bias[cg + 1];
            float2 v0 = make_float2(acc[i][j][0] + b0, acc[i][j][1] + b1);
            float2 v1 = make_float2(acc[i][j][2] + b0, acc[i][j][3] + b1);
            *(float2*)&C[(size_t)rg0 * N + cg]       = v0;
            *(float2*)&C[(size_t)(rg0 + 8) * N + cg] = v1;
        }
    }
}

// ---------------- depthwise causal conv(4) + silu ----------------
__global__ void conv_silu_kernel(const float* __restrict__ cw,
                                 const float* __restrict__ cb, int l)
{
    int idx = blockIdx.x * blockDim.x + threadIdx.x;
    if (idx >= TOKENS * (DINNER / 4)) return;
    int c4  = idx & 127;
    int tok = idx >> 7;
    int b   = tok / SEQ;
    int s   = tok % SEQ;
    int c   = c4 * 4;

    float4 w0 = *(const float4*)&cw[(l * DINNER + c + 0) * DCONV];
    float4 w1 = *(const float4*)&cw[(l * DINNER + c + 1) * DCONV];
    float4 w2 = *(const float4*)&cw[(l * DINNER + c + 2) * DCONV];
    float4 w3 = *(const float4*)&cw[(l * DINNER + c + 3) * DCONV];
    float wa[4][4] = {{w0.x,w0.y,w0.z,w0.w},{w1.x,w1.y,w1.z,w1.w},
                      {w2.x,w2.y,w2.z,w2.w},{w3.x,w3.y,w3.z,w3.w}};
    float out[4];
#pragma unroll
    for (int j = 0; j < 4; j++) out[j] = cb[l * DINNER + c + j];

#pragma unroll
    for (int k = 0; k < DCONV; k++) {
        int st = s - (DCONV - 1) + k;
        if (st >= 0) {
            float4 v = *(const float4*)&g_xz[(size_t)(b * SEQ + st) * 2 * DINNER + c];
            out[0] += v.x * wa[0][k];
            out[1] += v.y * wa[1][k];
            out[2] += v.z * wa[2][k];
            out[3] += v.w * wa[3][k];
        }
    }
    float4 r;
    r.x = out[0] * (1.f / (1.f + __expf(-out[0])));
    r.y = out[1] * (1.f / (1.f + __expf(-out[1])));
    r.z = out[2] * (1.f / (1.f + __expf(-out[2])));
    r.w = out[3] * (1.f / (1.f + __expf(-out[3])));
    *(float4*)&g_xs[(size_t)tok * DINNER + c] = r;
}

// ---------------- xproj: W staged in SMEM, 4 tokens per inner loop (fp32) ----------------
__global__ __launch_bounds__(256) void xproj_kernel(const float* __restrict__ W,
                                                    const float* __restrict__ bias, int l)
{
    extern __shared__ float Ws[];   // 512*32 floats = 64 KB
    int tid  = threadIdx.x;
    int lane = tid & 31;
    int warp = tid >> 5;

    const float* Wl = W + (size_t)l * DINNER * 32;
#pragma unroll
    for (int i = 0; i < 16; i++) {
        int li = (i * 256 + tid) * 4;
        *(float4*)&Ws[li] = *(const float4*)&Wl[li];
    }
    __syncthreads();

    float bv = bias[l * 32 + lane];
    int base = blockIdx.x * 128 + warp * 16;

#pragma unroll
    for (int g = 0; g < 4; g++) {
        int tok = base + g * 4;
        const float* x0 = g_xs + (size_t)(tok + 0) * DINNER;
        const float* x1 = g_xs + (size_t)(tok + 1) * DINNER;
        const float* x2 = g_xs + (size_t)(tok + 2) * DINNER;
        const float* x3 = g_xs + (size_t)(tok + 3) * DINNER;
        float a0 = bv, a1 = bv, a2 = bv, a3 = bv;
#pragma unroll 4
        for (int k = 0; k < DINNER; k += 4) {
            float w0 = Ws[(k + 0) * 32 + lane];
            float w1 = Ws[(k + 1) * 32 + lane];
            float w2 = Ws[(k + 2) * 32 + lane];
            float w3 = Ws[(k + 3) * 32 + lane];
            float4 v0 = *(const float4*)(x0 + k);
            float4 v1 = *(const float4*)(x1 + k);
            float4 v2 = *(const float4*)(x2 + k);
            float4 v3 = *(const float4*)(x3 + k);
            a0 += v0.x * w0 + v0.y * w1 + v0.z * w2 + v0.w * w3;
            a1 += v1.x * w0 + v1.y * w1 + v1.z * w2 + v1.w * w3;
            a2 += v2.x * w0 + v2.y * w1 + v2.z * w2 + v2.w * w3;
            a3 += v3.x * w0 + v3.y * w1 + v3.z * w2 + v3.w * w3;
        }
        if (lane < DSTATE) {
            a0 = (a0 > 20.f) ? a0 : log1pf(__expf(a0));
            a1 = (a1 > 20.f) ? a1 : log1pf(__expf(a1));
            a2 = (a2 > 20.f) ? a2 : log1pf(__expf(a2));
            a3 = (a3 > 20.f) ? a3 : log1pf(__expf(a3));
        }
        g_ssm[(size_t)(tok + 0) * 32 + lane] = a0;
        g_ssm[(size_t)(tok + 1) * 32 + lane] = a1;
        g_ssm[(size_t)(tok + 2) * 32 + lane] = a2;
        g_ssm[(size_t)(tok + 3) * 32 + lane] = a3;
    }
}

// ---------------- selective scan, fused with * silu(res) ----------------
__global__ __launch_bounds__(128) void scan_kernel(const float* __restrict__ A_log,
                                                   const float* __restrict__ Dp, int l)
{
    int b = blockIdx.x;
    int d = blockIdx.y * 128 + threadIdx.x;

    const float* Al = A_log + (l * DINNER + d) * DSTATE;
    float a2[DSTATE];
#pragma unroll
    for (int n = 0; n < DSTATE; n++) a2[n] = -__expf(Al[n]) * LOG2E;
    float Dv = Dp[l * DINNER + d];
    float h[DSTATE];
#pragma unroll
    for (int n = 0; n < DSTATE; n++) h[n] = 0.f;

    int tok0 = b * SEQ;
    const float* ssm = g_ssm + (size_t)tok0 * 32;
    const float* xsp = g_xs + (size_t)tok0 * DINNER + d;
    const float* rsp = g_xz + (size_t)tok0 * 2 * DINNER + DINNER + d;
    float*       yp  = g_y  + (size_t)tok0 * DINNER + d;

    for (int t = 0; t < SEQ; t++) {
        float4 d0 = *(const float4*)(ssm + 0);
        float4 d1 = *(const float4*)(ssm + 4);
        float4 d2 = *(const float4*)(ssm + 8);
        float4 d3 = *(const float4*)(ssm + 12);
        float4 b0 = *(const float4*)(ssm + 16);
        float4 b1 = *(const float4*)(ssm + 20);
        float4 b2 = *(const float4*)(ssm + 24);
        float4 b3 = *(const float4*)(ssm + 28);
        float dl[DSTATE] = {d0.x,d0.y,d0.z,d0.w, d1.x,d1.y,d1.z,d1.w,
                            d2.x,d2.y,d2.z,d2.w, d3.x,d3.y,d3.z,d3.w};
        float bm[DSTATE] = {b0.x,b0.y,b0.z,b0.w, b1.x,b1.y,b1.z,b1.w,
                            b2.x,b2.y,b2.z,b2.w, b3.x,b3.y,b3.z,b3.w};
        float xv = *xsp;
        float accv = 0.f;
#pragma unroll
        for (int n = 0; n < DSTATE; n++) {
            float e = exp2f(a2[n] * dl[n]);
            h[n] = h[n] * e + xv * bm[n];
            accv += h[n] * bm[n];
        }
        float r  = *rsp;
        float sl = r * (1.f / (1.f + __expf(-r)));
        *yp = (accv + Dv * xv) * sl;

        ssm += 32; xsp += DINNER; rsp += 2 * DINNER; yp += DINNER;
    }
}

// ---------------- residual add + layernorm ----------------
__global__ void add_ln_kernel(const float* __restrict__ gma,
                              const float* __restrict__ bta)
{
    int gw   = (blockIdx.x * blockDim.x + threadIdx.x) >> 5;
    int lane = threadIdx.x & 31;
    if (gw >= TOKENS) return;
    float* xr = g_x + (size_t)gw * DMODEL;
    const float* orow = g_o + (size_t)gw * DMODEL;

    float v[8];
    float sum = 0.f;
#pragma unroll
    for (int i = 0; i < 8; i++) {
        int c = lane + i * 32;
        v[i] = xr[c] + orow[c];
        sum += v[i];
    }
#pragma unroll
    for (int o = 16; o > 0; o >>= 1) sum += __shfl_xor_sync(0xFFFFFFFF, sum, o);
    float mu = sum * (1.f / DMODEL);
    float s2 = 0.f;
#pragma unroll
    for (int i = 0; i < 8; i++) { float dd = v[i] - mu; s2 += dd * dd; }
#pragma unroll
    for (int o = 16; o > 0; o >>= 1) s2 += __shfl_xor_sync(0xFFFFFFFF, s2, o);
    float rstd = rsqrtf(s2 * (1.f / DMODEL) + LN_EPS);
#pragma unroll
    for (int i = 0; i < 8; i++) {
        int c = lane + i * 32;
        xr[c] = (v[i] - mu) * rstd * gma[c] + bta[c];
    }
}

// ---------------- heads ----------------
__global__ void heads_kernel(const float* __restrict__ c1w, const float* __restrict__ c1b,
                             const float* __restrict__ c2w, const float* __restrict__ c2b,
                             const float* __restrict__ q1w, const float* __restrict__ q1b,
                             const float* __restrict__ q2w, const float* __restrict__ q2b,
                             float* __restrict__ out)
{
    __shared__ float fin[DMODEL];
    __shared__ float hc[128], hq[128];
    int b = blockIdx.x, t = threadIdx.x;
    const float* f = g_x + (size_t)(b * SEQ + SEQ - 1) * DMODEL;
    fin[t] = f[t];
    fin[t + 128] = f[t + 128];
    __syncthreads();
    float a1 = c1b[t], a2 = q1b[t];
#pragma unroll 4
    for (int k = 0; k < DMODEL; k++) {
        float fv = fin[k];
        a1 += fv * c1w[k * 128 + t];
        a2 += fv * q1w[k * 128 + t];
    }
    hc[t] = fmaxf(a1, 0.f);
    hq[t] = fmaxf(a2, 0.f);
    __syncthreads();
    if (t == 0) {
        float s = c2b[0];
        for (int k = 0; k < 128; k++) s += hc[k] * c2w[k];
        out[b] = fmaxf(s, 0.f);
    }
    if (t < 10) {
        float s = q2b[t];
        for (int k = 0; k < 128; k++) s += hq[k] * q2w[k * 10 + t];
        out[BATCH + b * 10 + t] = fmaxf(s, 0.f);
    }
}

// ---------------- launch ----------------
extern "C" void kernel_launch(void* const* d_in, const int* in_sizes, int n_in,
                              void* d_out, int out_size)
{
    const int*   grid   = (const int*)  d_in[0];
    const float* ce     = (const float*)d_in[1];
    const float* pe     = (const float*)d_in[2];
    const float* in_w   = (const float*)d_in[3];
    const float* in_b   = (const float*)d_in[4];
    const float* conv_w = (const float*)d_in[5];
    const float* conv_b = (const float*)d_in[6];
    const float* xp_w   = (const float*)d_in[7];
    const float* xp_b   = (const float*)d_in[8];
    const float* A_log  = (const float*)d_in[9];
    const float* Dp     = (const float*)d_in[10];
    const float* out_w  = (const float*)d_in[11];
    const float* out_b  = (const float*)d_in[12];
    const float* ln_g   = (const float*)d_in[13];
    const float* ln_b   = (const float*)d_in[14];
    const float* c1w    = (const float*)d_in[15];
    const float* c1b    = (const float*)d_in[16];
    const float* c2w    = (const float*)d_in[17];
    const float* c2b    = (const float*)d_in[18];
    const float* q1w    = (const float*)d_in[19];
    const float* q1b    = (const float*)d_in[20];
    const float* q2w    = (const float*)d_in[21];
    const float* q2b    = (const float*)d_in[22];
    float* out = (float*)d_out;

    float *px, *pxz, *pxs, *py, *po;
    uint32_t *pwbi, *pwbo;
    cudaGetSymbolAddress((void**)&px,   g_x);
    cudaGetSymbolAddress((void**)&pxz,  g_xz);
    cudaGetSymbolAddress((void**)&pxs,  g_xs);
    cudaGetSymbolAddress((void**)&py,   g_y);
    cudaGetSymbolAddress((void**)&po,   g_o);
    cudaGetSymbolAddress((void**)&pwbi, g_wbi);
    cudaGetSymbolAddress((void**)&pwbo, g_wbo);

    cudaFuncSetAttribute(xproj_kernel, cudaFuncAttributeMaxDynamicSharedMemorySize,
                         DINNER * 32 * (int)sizeof(float));

    // one-time weight convert+transpose to K-major bf16x2
    for (int l = 0; l < NLAYERS; l++) {
        int nin = 2 * DINNER * (DMODEL / 2);
        convert_w_kernel<<<(nin + 255) / 256, 256>>>(
            in_w + (size_t)l * DMODEL * 2 * DINNER,
            pwbi + (size_t)l * 2 * DINNER * (DMODEL / 2), DMODEL, 2 * DINNER);
        int nout = DMODEL * (DINNER / 2);
        convert_w_kernel<<<(nout + 255) / 256, 256>>>(
            out_w + (size_t)l * DINNER * DMODEL,
            pwbo + (size_t)l * DMODEL * (DINNER / 2), DINNER, DMODEL);
    }

    {
        int n = TOKENS * (DMODEL / 4);
        embed_kernel<<<(n + 255) / 256, 256>>>(grid, ce, pe);
    }

    for (int l = 0; l < NLAYERS; l++) {
        // in_proj: (T x 256) @ (256 x 1024)
        gemm_bf16_kernel<<<dim3(2 * DINNER / GBN, TOKENS / GBM), 256>>>(
            px, pwbi + (size_t)l * 2 * DINNER * (DMODEL / 2), in_b + l * 2 * DINNER, pxz,
            TOKENS, 2 * DINNER, DMODEL);

        {
            int n = TOKENS * (DINNER / 4);
            conv_silu_kernel<<<(n + 255) / 256, 256>>>(conv_w, conv_b, l);
        }

        // xproj (fp32, W in SMEM): (T x 512) @ (512 x 32), softplus fused
        xproj_kernel<<<TOKENS / 128, 256, DINNER * 32 * sizeof(float)>>>(xp_w, xp_b, l);

        scan_kernel<<<dim3(BATCH, DINNER / 128), 128>>>(A_log, Dp, l);

        // out_proj: (T x 512) @ (512 x 256)
        gemm_bf16_kernel<<<dim3(DMODEL / GBN, TOKENS / GBM), 256>>>(
            py, pwbo + (size_t)l * DMODEL * (DINNER / 2), out_b + l * DMODEL, po,
            TOKENS, DMODEL, DINNER);

        add_ln_kernel<<<(TOKENS * 32 + 255) / 256, 256>>>(ln_g, ln_b);
    }

    heads_kernel<<<BATCH, 128>>>(c1w, c1b, c2w, c2b, q1w, q1b, q2w, q2b, out);
}

// round 7
// speedup vs baseline: 1.6996x; 1.0318x over previous
#include <cuda_runtime.h>
#include <cuda_bf16.h>
#include <math.h>
#include <stdint.h>

#define NLAYERS 4
#define DMODEL  256
#define DINNER  512
#define DSTATE  16
#define DCONV   4
#define BATCH   64
#define SEQ     900
#define TOKENS  (BATCH * SEQ)   // 57600
#define LN_EPS  1e-5f
#define LOG2E   1.4426950408889634f

// ---------------- device scratch ----------------
__device__ float g_x  [TOKENS * DMODEL];            // residual stream (fp32)
__device__ __nv_bfloat16 g_xb[TOKENS * DMODEL];     // bf16 mirror of g_x
__device__ float g_xz [TOKENS * 2 * DINNER];        // in_proj out (xs | res)
__device__ float g_xs [TOKENS * DINNER];            // conv+silu out
__device__ float g_ssm[TOKENS * 2 * DSTATE];        // delta | B
__device__ __nv_bfloat16 g_yb[TOKENS * DINNER];     // scan out (bf16, feeds out_proj)
__device__ float g_o  [TOKENS * DMODEL];            // out_proj out
// K-major bf16 weights [N][K]
__device__ uint32_t g_wbi[NLAYERS * 2 * DINNER * (DMODEL / 2)];
__device__ uint32_t g_wbo[NLAYERS * DMODEL * (DINNER / 2)];

__device__ __forceinline__ uint32_t packbf(float lo, float hi) {
    uint32_t r;
    asm("cvt.rn.bf16x2.f32 %0, %1, %2;" : "=r"(r) : "f"(hi), "f"(lo));
    return r;
}
__device__ __forceinline__ uint32_t smem_u32(const void* p) {
    uint32_t a;
    asm("{ .reg .u64 t; cvta.to.shared.u64 t, %1; cvt.u32.u64 %0, t; }" : "=r"(a) : "l"(p));
    return a;
}
#define CP_ASYNC16(dst, src) \
    asm volatile("cp.async.cg.shared.global [%0], [%1], 16;" :: "r"(dst), "l"(src))
#define CP_COMMIT() asm volatile("cp.async.commit_group;" ::: "memory")
#define CP_WAIT2()  asm volatile("cp.async.wait_group 2;" ::: "memory")

// ---------------- weight convert+transpose ----------------
__global__ void convert_w_kernel(const float* __restrict__ w, uint32_t* __restrict__ wt,
                                 int K, int N)
{
    int idx = blockIdx.x * blockDim.x + threadIdx.x;
    if (idx >= N * (K / 2)) return;
    int n  = idx % N;
    int k2 = idx / N;
    float lo = w[(size_t)(2 * k2) * N + n];
    float hi = w[(size_t)(2 * k2 + 1) * N + n];
    wt[(size_t)n * (K / 2) + k2] = packbf(lo, hi);
}

// ---------------- embed (fp32 + bf16 mirror) ----------------
__global__ void embed_kernel(const int* __restrict__ grid,
                             const float* __restrict__ ce,
                             const float* __restrict__ pe)
{
    int idx = blockIdx.x * blockDim.x + threadIdx.x;
    if (idx >= TOKENS * (DMODEL / 4)) return;
    int tok = idx >> 6;
    int c4  = (idx & 63) * 4;
    int s   = tok % SEQ;
    int g   = grid[tok];
    float4 a = *(const float4*)&ce[g * DMODEL + c4];
    float4 p = *(const float4*)&pe[s * DMODEL + c4];
    float4 r; r.x = a.x + p.x; r.y = a.y + p.y; r.z = a.z + p.z; r.w = a.w + p.w;
    *(float4*)&g_x[tok * DMODEL + c4] = r;
    uint32_t pk0 = packbf(r.x, r.y);
    uint32_t pk1 = packbf(r.z, r.w);
    *(uint2*)&g_xb[tok * DMODEL + c4] = make_uint2(pk0, pk1);
}

// ---------------- bf16 GEMM: 128x128x32, 4-stage cp.async + ldmatrix ----------------
// A bf16 row-major [M][K], Bw bf16 K-major [N][K]. C fp32 = A@Bw^T + bias.
#define GSM_STAGE 20480            // A 128*80 + B 128*80 bytes
#define GSM_TOTAL (4 * GSM_STAGE)  // 81920

__device__ __forceinline__ void gemm_stage(uint32_t st,
                                           const __nv_bfloat16* __restrict__ A,
                                           const __nv_bfloat16* __restrict__ Bw,
                                           int row0, int col0, int K, int k0, int tid)
{
#pragma unroll
    for (int p = 0; p < 2; p++) {
        int i = tid + p * 256;
        int r = i >> 2, c = (i & 3) << 4;
        uint32_t dst = st + r * 80 + c;
        const char* src = (const char*)(A + (size_t)(row0 + r) * K + k0) + c;
        CP_ASYNC16(dst, src);
    }
#pragma unroll
    for (int p = 0; p < 2; p++) {
        int i = tid + p * 256;
        int r = i >> 2, c = (i & 3) << 4;
        uint32_t dst = st + 10240 + r * 80 + c;
        const char* src = (const char*)(Bw + (size_t)(col0 + r) * K + k0) + c;
        CP_ASYNC16(dst, src);
    }
}

__global__ __launch_bounds__(256, 2) void gemm_bf16_kernel(
    const __nv_bfloat16* __restrict__ A, const __nv_bfloat16* __restrict__ Bw,
    const float* __restrict__ bias, float* __restrict__ C,
    int M, int N, int K)
{
    extern __shared__ char smem[];
    uint32_t sb = smem_u32(smem);

    int tid  = threadIdx.x;
    int lane = tid & 31;
    int warp = tid >> 5;
    int wm   = warp >> 2;          // 0..1
    int wn   = warp & 3;           // 0..3
    int row0 = blockIdx.y * 128;
    int col0 = blockIdx.x * 128;
    int grp  = lane >> 2;
    int qid  = lane & 3;

    float acc[4][4][4];
#pragma unroll
    for (int i = 0; i < 4; i++)
#pragma unroll
        for (int j = 0; j < 4; j++)
#pragma unroll
            for (int r = 0; r < 4; r++) acc[i][j][r] = 0.f;

    int NC = K / 32;

    // prologue: stages 0..2
#pragma unroll
    for (int s = 0; s < 3; s++) {
        gemm_stage(sb + s * GSM_STAGE, A, Bw, row0, col0, K, s * 32, tid);
        CP_COMMIT();
    }

    // ldmatrix addresses (per-warp constant parts)
    int a_row = wm * 64 + (lane & 15);
    int a_koff = (lane >> 4) << 4;            // 0 or 16 bytes
    int b_row0 = wn * 32 + ((lane >> 4) << 3) + (lane & 7);
    int b_koff = ((lane >> 3) & 1) << 4;

    for (int c = 0; c < NC; c++) {
        CP_WAIT2();
        __syncthreads();
        if (c + 3 < NC) {
            gemm_stage(sb + ((c + 3) & 3) * GSM_STAGE, A, Bw, row0, col0, K, (c + 3) * 32, tid);
            CP_COMMIT();
        }
        uint32_t stA = sb + (c & 3) * GSM_STAGE;
        uint32_t stB = stA + 10240;
#pragma unroll
        for (int ks = 0; ks < 2; ks++) {
            uint32_t af[4][4];
#pragma unroll
            for (int i = 0; i < 4; i++) {
                uint32_t addr = stA + (a_row + i * 16) * 80 + ks * 32 + a_koff;
                asm volatile("ldmatrix.sync.aligned.m8n8.x4.shared.b16 {%0,%1,%2,%3}, [%4];"
                             : "=r"(af[i][0]), "=r"(af[i][1]), "=r"(af[i][2]), "=r"(af[i][3])
                             : "r"(addr));
            }
            uint32_t bf_[2][4];
#pragma unroll
            for (int jj = 0; jj < 2; jj++) {
                uint32_t addr = stB + (b_row0 + jj * 16) * 80 + ks * 32 + b_koff;
                asm volatile("ldmatrix.sync.aligned.m8n8.x4.shared.b16 {%0,%1,%2,%3}, [%4];"
                             : "=r"(bf_[jj][0]), "=r"(bf_[jj][1]), "=r"(bf_[jj][2]), "=r"(bf_[jj][3])
                             : "r"(addr));
            }
#pragma unroll
            for (int i = 0; i < 4; i++)
#pragma unroll
                for (int j = 0; j < 4; j++) {
                    asm volatile(
                        "mma.sync.aligned.m16n8k16.row.col.f32.bf16.bf16.f32 "
                        "{%0,%1,%2,%3}, {%4,%5,%6,%7}, {%8,%9}, {%0,%1,%2,%3};"
                        : "+f"(acc[i][j][0]), "+f"(acc[i][j][1]),
                          "+f"(acc[i][j][2]), "+f"(acc[i][j][3])
                        : "r"(af[i][0]), "r"(af[i][1]), "r"(af[i][2]), "r"(af[i][3]),
                          "r"(bf_[j >> 1][(j & 1) * 2]), "r"(bf_[j >> 1][(j & 1) * 2 + 1]));
                }
        }
        __syncthreads();
    }

    // epilogue: bias + fp32 store
#pragma unroll
    for (int i = 0; i < 4; i++) {
        int rg0 = row0 + wm * 64 + i * 16 + grp;
#pragma unroll
        for (int j = 0; j < 4; j++) {
            int cg = col0 + wn * 32 + j * 8 + qid * 2;
            float b0 = bias[cg], b1 = bias[cg + 1];
            float2 v0 = make_float2(acc[i][j][0] + b0, acc[i][j][1] + b1);
            float2 v1 = make_float2(acc[i][j][2] + b0, acc[i][j][3] + b1);
            *(float2*)&C[(size_t)rg0 * N + cg]       = v0;
            *(float2*)&C[(size_t)(rg0 + 8) * N + cg] = v1;
        }
    }
}

// ---------------- depthwise causal conv(4) + silu ----------------
__global__ void conv_silu_kernel(const float* __restrict__ cw,
                                 const float* __restrict__ cb, int l)
{
    int idx = blockIdx.x * blockDim.x + threadIdx.x;
    if (idx >= TOKENS * (DINNER / 4)) return;
    int c4  = idx & 127;
    int tok = idx >> 7;
    int b   = tok / SEQ;
    int s   = tok % SEQ;
    int c   = c4 * 4;

    float4 w0 = *(const float4*)&cw[(l * DINNER + c + 0) * DCONV];
    float4 w1 = *(const float4*)&cw[(l * DINNER + c + 1) * DCONV];
    float4 w2 = *(const float4*)&cw[(l * DINNER + c + 2) * DCONV];
    float4 w3 = *(const float4*)&cw[(l * DINNER + c + 3) * DCONV];
    float wa[4][4] = {{w0.x,w0.y,w0.z,w0.w},{w1.x,w1.y,w1.z,w1.w},
                      {w2.x,w2.y,w2.z,w2.w},{w3.x,w3.y,w3.z,w3.w}};
    float out[4];
#pragma unroll
    for (int j = 0; j < 4; j++) out[j] = cb[l * DINNER + c + j];

#pragma unroll
    for (int k = 0; k < DCONV; k++) {
        int st = s - (DCONV - 1) + k;
        if (st >= 0) {
            float4 v = *(const float4*)&g_xz[(size_t)(b * SEQ + st) * 2 * DINNER + c];
            out[0] += v.x * wa[0][k];
            out[1] += v.y * wa[1][k];
            out[2] += v.z * wa[2][k];
            out[3] += v.w * wa[3][k];
        }
    }
    float4 r;
    r.x = out[0] * (1.f / (1.f + __expf(-out[0])));
    r.y = out[1] * (1.f / (1.f + __expf(-out[1])));
    r.z = out[2] * (1.f / (1.f + __expf(-out[2])));
    r.w = out[3] * (1.f / (1.f + __expf(-out[3])));
    *(float4*)&g_xs[(size_t)tok * DINNER + c] = r;
}

// ---------------- xproj (fp32, W in SMEM) ----------------
__global__ __launch_bounds__(256) void xproj_kernel(const float* __restrict__ W,
                                                    const float* __restrict__ bias, int l)
{
    extern __shared__ float Ws[];
    int tid  = threadIdx.x;
    int lane = tid & 31;
    int warp = tid >> 5;

    const float* Wl = W + (size_t)l * DINNER * 32;
#pragma unroll
    for (int i = 0; i < 16; i++) {
        int li = (i * 256 + tid) * 4;
        *(float4*)&Ws[li] = *(const float4*)&Wl[li];
    }
    __syncthreads();

    float bv = bias[l * 32 + lane];
    int base = blockIdx.x * 128 + warp * 16;

#pragma unroll
    for (int g = 0; g < 4; g++) {
        int tok = base + g * 4;
        const float* x0 = g_xs + (size_t)(tok + 0) * DINNER;
        const float* x1 = g_xs + (size_t)(tok + 1) * DINNER;
        const float* x2 = g_xs + (size_t)(tok + 2) * DINNER;
        const float* x3 = g_xs + (size_t)(tok + 3) * DINNER;
        float a0 = bv, a1 = bv, a2 = bv, a3 = bv;
#pragma unroll 4
        for (int k = 0; k < DINNER; k += 4) {
            float w0 = Ws[(k + 0) * 32 + lane];
            float w1 = Ws[(k + 1) * 32 + lane];
            float w2 = Ws[(k + 2) * 32 + lane];
            float w3 = Ws[(k + 3) * 32 + lane];
            float4 v0 = *(const float4*)(x0 + k);
            float4 v1 = *(const float4*)(x1 + k);
            float4 v2 = *(const float4*)(x2 + k);
            float4 v3 = *(const float4*)(x3 + k);
            a0 += v0.x * w0 + v0.y * w1 + v0.z * w2 + v0.w * w3;
            a1 += v1.x * w0 + v1.y * w1 + v1.z * w2 + v1.w * w3;
            a2 += v2.x * w0 + v2.y * w1 + v2.z * w2 + v2.w * w3;
            a3 += v3.x * w0 + v3.y * w1 + v3.z * w2 + v3.w * w3;
        }
        if (lane < DSTATE) {
            a0 = (a0 > 20.f) ? a0 : log1pf(__expf(a0));
            a1 = (a1 > 20.f) ? a1 : log1pf(__expf(a1));
            a2 = (a2 > 20.f) ? a2 : log1pf(__expf(a2));
            a3 = (a3 > 20.f) ? a3 : log1pf(__expf(a3));
        }
        g_ssm[(size_t)(tok + 0) * 32 + lane] = a0;
        g_ssm[(size_t)(tok + 1) * 32 + lane] = a1;
        g_ssm[(size_t)(tok + 2) * 32 + lane] = a2;
        g_ssm[(size_t)(tok + 3) * 32 + lane] = a3;
    }
}

// ---------------- selective scan (writes bf16 y) ----------------
__global__ __launch_bounds__(128) void scan_kernel(const float* __restrict__ A_log,
                                                   const float* __restrict__ Dp, int l)
{
    int b = blockIdx.x;
    int d = blockIdx.y * 128 + threadIdx.x;

    const float* Al = A_log + (l * DINNER + d) * DSTATE;
    float a2[DSTATE];
#pragma unroll
    for (int n = 0; n < DSTATE; n++) a2[n] = -__expf(Al[n]) * LOG2E;
    float Dv = Dp[l * DINNER + d];
    float h[DSTATE];
#pragma unroll
    for (int n = 0; n < DSTATE; n++) h[n] = 0.f;

    int tok0 = b * SEQ;
    const float* ssm = g_ssm + (size_t)tok0 * 32;
    const float* xsp = g_xs + (size_t)tok0 * DINNER + d;
    const float* rsp = g_xz + (size_t)tok0 * 2 * DINNER + DINNER + d;
    __nv_bfloat16* yp = g_yb + (size_t)tok0 * DINNER + d;

    for (int t = 0; t < SEQ; t++) {
        float4 d0 = *(const float4*)(ssm + 0);
        float4 d1 = *(const float4*)(ssm + 4);
        float4 d2 = *(const float4*)(ssm + 8);
        float4 d3 = *(const float4*)(ssm + 12);
        float4 b0 = *(const float4*)(ssm + 16);
        float4 b1 = *(const float4*)(ssm + 20);
        float4 b2 = *(const float4*)(ssm + 24);
        float4 b3 = *(const float4*)(ssm + 28);
        float dl[DSTATE] = {d0.x,d0.y,d0.z,d0.w, d1.x,d1.y,d1.z,d1.w,
                            d2.x,d2.y,d2.z,d2.w, d3.x,d3.y,d3.z,d3.w};
        float bm[DSTATE] = {b0.x,b0.y,b0.z,b0.w, b1.x,b1.y,b1.z,b1.w,
                            b2.x,b2.y,b2.z,b2.w, b3.x,b3.y,b3.z,b3.w};
        float xv = *xsp;
        float accv = 0.f;
#pragma unroll
        for (int n = 0; n < DSTATE; n++) {
            float e = exp2f(a2[n] * dl[n]);
            h[n] = h[n] * e + xv * bm[n];
            accv += h[n] * bm[n];
        }
        float r  = *rsp;
        float sl = r * (1.f / (1.f + __expf(-r)));
        *yp = __float2bfloat16((accv + Dv * xv) * sl);

        ssm += 32; xsp += DINNER; rsp += 2 * DINNER; yp += DINNER;
    }
}

// ---------------- residual add + layernorm (fp32 + bf16 mirror) ----------------
__global__ void add_ln_kernel(const float* __restrict__ gma,
                              const float* __restrict__ bta)
{
    int gw   = (blockIdx.x * blockDim.x + threadIdx.x) >> 5;
    int lane = threadIdx.x & 31;
    if (gw >= TOKENS) return;
    float* xr = g_x + (size_t)gw * DMODEL;
    __nv_bfloat16* xb = g_xb + (size_t)gw * DMODEL;
    const float* orow = g_o + (size_t)gw * DMODEL;

    float v[8];
    float sum = 0.f;
#pragma unroll
    for (int i = 0; i < 8; i++) {
        int c = lane + i * 32;
        v[i] = xr[c] + orow[c];
        sum += v[i];
    }
#pragma unroll
    for (int o = 16; o > 0; o >>= 1) sum += __shfl_xor_sync(0xFFFFFFFF, sum, o);
    float mu = sum * (1.f / DMODEL);
    float s2 = 0.f;
#pragma unroll
    for (int i = 0; i < 8; i++) { float dd = v[i] - mu; s2 += dd * dd; }
#pragma unroll
    for (int o = 16; o > 0; o >>= 1) s2 += __shfl_xor_sync(0xFFFFFFFF, s2, o);
    float rstd = rsqrtf(s2 * (1.f / DMODEL) + LN_EPS);
#pragma unroll
    for (int i = 0; i < 8; i++) {
        int c = lane + i * 32;
        float nv = (v[i] - mu) * rstd * gma[c] + bta[c];
        xr[c] = nv;
        xb[c] = __float2bfloat16(nv);
    }
}

// ---------------- heads ----------------
__global__ void heads_kernel(const float* __restrict__ c1w, const float* __restrict__ c1b,
                             const float* __restrict__ c2w, const float* __restrict__ c2b,
                             const float* __restrict__ q1w, const float* __restrict__ q1b,
                             const float* __restrict__ q2w, const float* __restrict__ q2b,
                             float* __restrict__ out)
{
    __shared__ float fin[DMODEL];
    __shared__ float hc[128], hq[128];
    int b = blockIdx.x, t = threadIdx.x;
    const float* f = g_x + (size_t)(b * SEQ + SEQ - 1) * DMODEL;
    fin[t] = f[t];
    fin[t + 128] = f[t + 128];
    __syncthreads();
    float a1 = c1b[t], a2 = q1b[t];
#pragma unroll 4
    for (int k = 0; k < DMODEL; k++) {
        float fv = fin[k];
        a1 += fv * c1w[k * 128 + t];
        a2 += fv * q1w[k * 128 + t];
    }
    hc[t] = fmaxf(a1, 0.f);
    hq[t] = fmaxf(a2, 0.f);
    __syncthreads();
    if (t == 0) {
        float s = c2b[0];
        for (int k = 0; k < 128; k++) s += hc[k] * c2w[k];
        out[b] = fmaxf(s, 0.f);
    }
    if (t < 10) {
        float s = q2b[t];
        for (int k = 0; k < 128; k++) s += hq[k] * q2w[k * 10 + t];
        out[BATCH + b * 10 + t] = fmaxf(s, 0.f);
    }
}

// ---------------- launch ----------------
extern "C" void kernel_launch(void* const* d_in, const int* in_sizes, int n_in,
                              void* d_out, int out_size)
{
    const int*   grid   = (const int*)  d_in[0];
    const float* ce     = (const float*)d_in[1];
    const float* pe     = (const float*)d_in[2];
    const float* in_w   = (const float*)d_in[3];
    const float* in_b   = (const float*)d_in[4];
    const float* conv_w = (const float*)d_in[5];
    const float* conv_b = (const float*)d_in[6];
    const float* xp_w   = (const float*)d_in[7];
    const float* xp_b   = (const float*)d_in[8];
    const float* A_log  = (const float*)d_in[9];
    const float* Dp     = (const float*)d_in[10];
    const float* out_w  = (const float*)d_in[11];
    const float* out_b  = (const float*)d_in[12];
    const float* ln_g   = (const float*)d_in[13];
    const float* ln_b   = (const float*)d_in[14];
    const float* c1w    = (const float*)d_in[15];
    const float* c1b    = (const float*)d_in[16];
    const float* c2w    = (const float*)d_in[17];
    const float* c2b    = (const float*)d_in[18];
    const float* q1w    = (const float*)d_in[19];
    const float* q1b    = (const float*)d_in[20];
    const float* q2w    = (const float*)d_in[21];
    const float* q2b    = (const float*)d_in[22];
    float* out = (float*)d_out;

    __nv_bfloat16 *pxb, *pyb;
    uint32_t *pwbi, *pwbo;
    float *pxz, *po;
    cudaGetSymbolAddress((void**)&pxb,  g_xb);
    cudaGetSymbolAddress((void**)&pyb,  g_yb);
    cudaGetSymbolAddress((void**)&pxz,  g_xz);
    cudaGetSymbolAddress((void**)&po,   g_o);
    cudaGetSymbolAddress((void**)&pwbi, g_wbi);
    cudaGetSymbolAddress((void**)&pwbo, g_wbo);

    cudaFuncSetAttribute(xproj_kernel, cudaFuncAttributeMaxDynamicSharedMemorySize,
                         DINNER * 32 * (int)sizeof(float));
    cudaFuncSetAttribute(gemm_bf16_kernel, cudaFuncAttributeMaxDynamicSharedMemorySize,
                         GSM_TOTAL);

    // one-time weight convert+transpose
    for (int l = 0; l < NLAYERS; l++) {
        int nin = 2 * DINNER * (DMODEL / 2);
        convert_w_kernel<<<(nin + 255) / 256, 256>>>(
            in_w + (size_t)l * DMODEL * 2 * DINNER,
            pwbi + (size_t)l * 2 * DINNER * (DMODEL / 2), DMODEL, 2 * DINNER);
        int nout = DMODEL * (DINNER / 2);
        convert_w_kernel<<<(nout + 255) / 256, 256>>>(
            out_w + (size_t)l * DINNER * DMODEL,
            pwbo + (size_t)l * DMODEL * (DINNER / 2), DINNER, DMODEL);
    }

    {
        int n = TOKENS * (DMODEL / 4);
        embed_kernel<<<(n + 255) / 256, 256>>>(grid, ce, pe);
    }

    for (int l = 0; l < NLAYERS; l++) {
        // in_proj: (T x 256) @ (256 x 1024)
        gemm_bf16_kernel<<<dim3(2 * DINNER / 128, TOKENS / 128), 256, GSM_TOTAL>>>(
            pxb, (const __nv_bfloat16*)(pwbi + (size_t)l * 2 * DINNER * (DMODEL / 2)),
            in_b + l * 2 * DINNER, pxz, TOKENS, 2 * DINNER, DMODEL);

        {
            int n = TOKENS * (DINNER / 4);
            conv_silu_kernel<<<(n + 255) / 256, 256>>>(conv_w, conv_b, l);
        }

        xproj_kernel<<<TOKENS / 128, 256, DINNER * 32 * sizeof(float)>>>(xp_w, xp_b, l);

        scan_kernel<<<dim3(BATCH, DINNER / 128), 128>>>(A_log, Dp, l);

        // out_proj: (T x 512) @ (512 x 256)
        gemm_bf16_kernel<<<dim3(DMODEL / 128, TOKENS / 128), 256, GSM_TOTAL>>>(
            pyb, (const __nv_bfloat16*)(pwbo + (size_t)l * DMODEL * (DINNER / 2)),
            out_b + l * DMODEL, po, TOKENS, DMODEL, DINNER);

        add_ln_kernel<<<(TOKENS * 32 + 255) / 256, 256>>>(ln_g, ln_b);
    }

    heads_kernel<<<BATCH, 128>>>(c1w, c1b, c2w, c2b, q1w, q1b, q2w, q2b, out);
}

// round 8
// speedup vs baseline: 2.3717x; 1.3955x over previous
#include <cuda_runtime.h>
#include <cuda_bf16.h>
#include <math.h>
#include <stdint.h>

#define NLAYERS 4
#define DMODEL  256
#define DINNER  512
#define DSTATE  16
#define DCONV   4
#define BATCH   64
#define SEQ     900
#define TOKENS  (BATCH * SEQ)   // 57600
#define LN_EPS  1e-5f
#define LOG2E   1.4426950408889634f

// ---------------- device scratch ----------------
__device__ float g_x  [TOKENS * DMODEL];            // residual stream (fp32)
__device__ __nv_bfloat16 g_xb[TOKENS * DMODEL];     // bf16 mirror of g_x
__device__ __nv_bfloat16 g_xz[TOKENS * 2 * DINNER]; // in_proj out (xs | res), bf16
__device__ __nv_bfloat16 g_xs[TOKENS * DINNER];     // conv+silu out, bf16
__device__ float g_ssm[TOKENS * 2 * DSTATE];        // delta | B (fp32)
__device__ __nv_bfloat16 g_yb[TOKENS * DINNER];     // scan out (bf16)
__device__ float g_o  [TOKENS * DMODEL];            // out_proj out (fp32)
// K-major bf16 weights [N][K] (bf16x2-packed u32)
__device__ uint32_t g_wbi[NLAYERS * 2 * DINNER * (DMODEL / 2)];
__device__ uint32_t g_wbo[NLAYERS * DMODEL * (DINNER / 2)];

__device__ __forceinline__ uint32_t packbf(float lo, float hi) {
    uint32_t r;
    asm("cvt.rn.bf16x2.f32 %0, %1, %2;" : "=r"(r) : "f"(hi), "f"(lo));
    return r;
}
__device__ __forceinline__ uint32_t smem_u32(const void* p) {
    uint32_t a;
    asm("{ .reg .u64 t; cvta.to.shared.u64 t, %1; cvt.u32.u64 %0, t; }" : "=r"(a) : "l"(p));
    return a;
}
#define CP_ASYNC16(dst, src) \
    asm volatile("cp.async.cg.shared.global [%0], [%1], 16;" :: "r"(dst), "l"(src))
#define CP_COMMIT() asm volatile("cp.async.commit_group;" ::: "memory")
#define CP_WAIT1()  asm volatile("cp.async.wait_group 1;" ::: "memory")
#define CP_WAIT2()  asm volatile("cp.async.wait_group 2;" ::: "memory")

// ---------------- weight converts (2 launches total) ----------------
__global__ void convert_in_w_kernel(const float* __restrict__ w, uint32_t* __restrict__ wt)
{
    const int PER = 2 * DINNER * (DMODEL / 2);  // 131072
    int idx = blockIdx.x * blockDim.x + threadIdx.x;
    if (idx >= NLAYERS * PER) return;
    int l  = idx / PER;
    int r  = idx % PER;
    int n  = r % (2 * DINNER);
    int k2 = r / (2 * DINNER);
    const float* wl = w + (size_t)l * DMODEL * 2 * DINNER;
    float lo = wl[(size_t)(2 * k2) * 2 * DINNER + n];
    float hi = wl[(size_t)(2 * k2 + 1) * 2 * DINNER + n];
    wt[(size_t)l * PER + (size_t)n * (DMODEL / 2) + k2] = packbf(lo, hi);
}
__global__ void convert_out_w_kernel(const float* __restrict__ w, uint32_t* __restrict__ wt)
{
    const int PER = DMODEL * (DINNER / 2);      // 65536
    int idx = blockIdx.x * blockDim.x + threadIdx.x;
    if (idx >= NLAYERS * PER) return;
    int l  = idx / PER;
    int r  = idx % PER;
    int n  = r % DMODEL;
    int k2 = r / DMODEL;
    const float* wl = w + (size_t)l * DINNER * DMODEL;
    float lo = wl[(size_t)(2 * k2) * DMODEL + n];
    float hi = wl[(size_t)(2 * k2 + 1) * DMODEL + n];
    wt[(size_t)l * PER + (size_t)n * (DINNER / 2) + k2] = packbf(lo, hi);
}

// ---------------- embed (fp32 + bf16 mirror) ----------------
__global__ void embed_kernel(const int* __restrict__ grid,
                             const float* __restrict__ ce,
                             const float* __restrict__ pe)
{
    int idx = blockIdx.x * blockDim.x + threadIdx.x;
    if (idx >= TOKENS * (DMODEL / 4)) return;
    int tok = idx >> 6;
    int c4  = (idx & 63) * 4;
    int s   = tok % SEQ;
    int g   = grid[tok];
    float4 a = *(const float4*)&ce[g * DMODEL + c4];
    float4 p = *(const float4*)&pe[s * DMODEL + c4];
    float4 r; r.x = a.x + p.x; r.y = a.y + p.y; r.z = a.z + p.z; r.w = a.w + p.w;
    *(float4*)&g_x[tok * DMODEL + c4] = r;
    *(uint2*)&g_xb[tok * DMODEL + c4] = make_uint2(packbf(r.x, r.y), packbf(r.z, r.w));
}

// ---------------- bf16 GEMM: 128x128x32, 4-stage cp.async + ldmatrix ----------------
#define GSM_STAGE 20480
#define GSM_TOTAL (4 * GSM_STAGE)

__device__ __forceinline__ void gemm_stage(uint32_t st,
                                           const __nv_bfloat16* __restrict__ A,
                                           const __nv_bfloat16* __restrict__ Bw,
                                           int row0, int col0, int K, int k0, int tid)
{
#pragma unroll
    for (int p = 0; p < 2; p++) {
        int i = tid + p * 256;
        int r = i >> 2, c = (i & 3) << 4;
        CP_ASYNC16(st + r * 80 + c,
                   (const char*)(A + (size_t)(row0 + r) * K + k0) + c);
    }
#pragma unroll
    for (int p = 0; p < 2; p++) {
        int i = tid + p * 256;
        int r = i >> 2, c = (i & 3) << 4;
        CP_ASYNC16(st + 10240 + r * 80 + c,
                   (const char*)(Bw + (size_t)(col0 + r) * K + k0) + c);
    }
}

template<int OUTBF>
__global__ __launch_bounds__(256, 2) void gemm_bf16_kernel(
    const __nv_bfloat16* __restrict__ A, const __nv_bfloat16* __restrict__ Bw,
    const float* __restrict__ bias, void* __restrict__ Cv,
    int M, int N, int K)
{
    extern __shared__ char smem[];
    uint32_t sb = smem_u32(smem);

    int tid  = threadIdx.x;
    int lane = tid & 31;
    int warp = tid >> 5;
    int wm   = warp >> 2;
    int wn   = warp & 3;
    int row0 = blockIdx.y * 128;
    int col0 = blockIdx.x * 128;
    int grp  = lane >> 2;
    int qid  = lane & 3;

    float acc[4][4][4];
#pragma unroll
    for (int i = 0; i < 4; i++)
#pragma unroll
        for (int j = 0; j < 4; j++)
#pragma unroll
            for (int r = 0; r < 4; r++) acc[i][j][r] = 0.f;

    int NC = K / 32;
#pragma unroll
    for (int s = 0; s < 3; s++) {
        gemm_stage(sb + s * GSM_STAGE, A, Bw, row0, col0, K, s * 32, tid);
        CP_COMMIT();
    }

    int a_row  = wm * 64 + (lane & 15);
    int a_koff = (lane >> 4) << 4;
    int b_row0 = wn * 32 + ((lane >> 4) << 3) + (lane & 7);
    int b_koff = ((lane >> 3) & 1) << 4;

    for (int c = 0; c < NC; c++) {
        CP_WAIT2();
        __syncthreads();
        if (c + 3 < NC) {
            gemm_stage(sb + ((c + 3) & 3) * GSM_STAGE, A, Bw, row0, col0, K, (c + 3) * 32, tid);
            CP_COMMIT();
        }
        uint32_t stA = sb + (c & 3) * GSM_STAGE;
        uint32_t stB = stA + 10240;
#pragma unroll
        for (int ks = 0; ks < 2; ks++) {
            uint32_t af[4][4];
#pragma unroll
            for (int i = 0; i < 4; i++) {
                uint32_t addr = stA + (a_row + i * 16) * 80 + ks * 32 + a_koff;
                asm volatile("ldmatrix.sync.aligned.m8n8.x4.shared.b16 {%0,%1,%2,%3}, [%4];"
                             : "=r"(af[i][0]), "=r"(af[i][1]), "=r"(af[i][2]), "=r"(af[i][3])
                             : "r"(addr));
            }
            uint32_t bf_[2][4];
#pragma unroll
            for (int jj = 0; jj < 2; jj++) {
                uint32_t addr = stB + (b_row0 + jj * 16) * 80 + ks * 32 + b_koff;
                asm volatile("ldmatrix.sync.aligned.m8n8.x4.shared.b16 {%0,%1,%2,%3}, [%4];"
                             : "=r"(bf_[jj][0]), "=r"(bf_[jj][1]), "=r"(bf_[jj][2]), "=r"(bf_[jj][3])
                             : "r"(addr));
            }
#pragma unroll
            for (int i = 0; i < 4; i++)
#pragma unroll
                for (int j = 0; j < 4; j++) {
                    asm volatile(
                        "mma.sync.aligned.m16n8k16.row.col.f32.bf16.bf16.f32 "
                        "{%0,%1,%2,%3}, {%4,%5,%6,%7}, {%8,%9}, {%0,%1,%2,%3};"
                        : "+f"(acc[i][j][0]), "+f"(acc[i][j][1]),
                          "+f"(acc[i][j][2]), "+f"(acc[i][j][3])
                        : "r"(af[i][0]), "r"(af[i][1]), "r"(af[i][2]), "r"(af[i][3]),
                          "r"(bf_[j >> 1][(j & 1) * 2]), "r"(bf_[j >> 1][(j & 1) * 2 + 1]));
                }
        }
        __syncthreads();
    }

#pragma unroll
    for (int i = 0; i < 4; i++) {
        int rg0 = row0 + wm * 64 + i * 16 + grp;
#pragma unroll
        for (int j = 0; j < 4; j++) {
            int cg = col0 + wn * 32 + j * 8 + qid * 2;
            float b0 = bias[cg], b1 = bias[cg + 1];
            if (OUTBF) {
                __nv_bfloat16* Cb = (__nv_bfloat16*)Cv;
                *(uint32_t*)&Cb[(size_t)rg0 * N + cg]       = packbf(acc[i][j][0] + b0, acc[i][j][1] + b1);
                *(uint32_t*)&Cb[(size_t)(rg0 + 8) * N + cg] = packbf(acc[i][j][2] + b0, acc[i][j][3] + b1);
            } else {
                float* C = (float*)Cv;
                *(float2*)&C[(size_t)rg0 * N + cg]       = make_float2(acc[i][j][0] + b0, acc[i][j][1] + b1);
                *(float2*)&C[(size_t)(rg0 + 8) * N + cg] = make_float2(acc[i][j][2] + b0, acc[i][j][3] + b1);
            }
        }
    }
}

// ---------------- depthwise causal conv(4) + silu (bf16 in/out) ----------------
__global__ void conv_silu_kernel(const float* __restrict__ cw,
                                 const float* __restrict__ cb, int l)
{
    int idx = blockIdx.x * blockDim.x + threadIdx.x;
    if (idx >= TOKENS * (DINNER / 4)) return;
    int c4  = idx & 127;
    int tok = idx >> 7;
    int b   = tok / SEQ;
    int s   = tok % SEQ;
    int c   = c4 * 4;

    float4 w0 = *(const float4*)&cw[(l * DINNER + c + 0) * DCONV];
    float4 w1 = *(const float4*)&cw[(l * DINNER + c + 1) * DCONV];
    float4 w2 = *(const float4*)&cw[(l * DINNER + c + 2) * DCONV];
    float4 w3 = *(const float4*)&cw[(l * DINNER + c + 3) * DCONV];
    float wa[4][4] = {{w0.x,w0.y,w0.z,w0.w},{w1.x,w1.y,w1.z,w1.w},
                      {w2.x,w2.y,w2.z,w2.w},{w3.x,w3.y,w3.z,w3.w}};
    float out[4];
#pragma unroll
    for (int j = 0; j < 4; j++) out[j] = cb[l * DINNER + c + j];

#pragma unroll
    for (int k = 0; k < DCONV; k++) {
        int st = s - (DCONV - 1) + k;
        if (st >= 0) {
            uint2 v = *(const uint2*)&g_xz[(size_t)(b * SEQ + st) * 2 * DINNER + c];
            float2 p0 = __bfloat1622float2(*(__nv_bfloat162*)&v.x);
            float2 p1 = __bfloat1622float2(*(__nv_bfloat162*)&v.y);
            out[0] += p0.x * wa[0][k];
            out[1] += p0.y * wa[1][k];
            out[2] += p1.x * wa[2][k];
            out[3] += p1.y * wa[3][k];
        }
    }
    float s0 = out[0] * (1.f / (1.f + __expf(-out[0])));
    float s1 = out[1] * (1.f / (1.f + __expf(-out[1])));
    float s2 = out[2] * (1.f / (1.f + __expf(-out[2])));
    float s3 = out[3] * (1.f / (1.f + __expf(-out[3])));
    *(uint2*)&g_xs[(size_t)tok * DINNER + c] = make_uint2(packbf(s0, s1), packbf(s2, s3));
}

// ---------------- xproj (bf16 xs, fp32 W in SMEM) ----------------
__global__ __launch_bounds__(256) void xproj_kernel(const float* __restrict__ W,
                                                    const float* __restrict__ bias, int l)
{
    extern __shared__ float Ws[];
    int tid  = threadIdx.x;
    int lane = tid & 31;
    int warp = tid >> 5;

    const float* Wl = W + (size_t)l * DINNER * 32;
#pragma unroll
    for (int i = 0; i < 16; i++) {
        int li = (i * 256 + tid) * 4;
        *(float4*)&Ws[li] = *(const float4*)&Wl[li];
    }
    __syncthreads();

    float bv = bias[l * 32 + lane];
    int base = blockIdx.x * 128 + warp * 16;

#pragma unroll
    for (int g = 0; g < 4; g++) {
        int tok = base + g * 4;
        const __nv_bfloat16* x0 = g_xs + (size_t)(tok + 0) * DINNER;
        const __nv_bfloat16* x1 = g_xs + (size_t)(tok + 1) * DINNER;
        const __nv_bfloat16* x2 = g_xs + (size_t)(tok + 2) * DINNER;
        const __nv_bfloat16* x3 = g_xs + (size_t)(tok + 3) * DINNER;
        float a0 = bv, a1 = bv, a2 = bv, a3 = bv;
#pragma unroll 4
        for (int k = 0; k < DINNER; k += 4) {
            float w0 = Ws[(k + 0) * 32 + lane];
            float w1 = Ws[(k + 1) * 32 + lane];
            float w2 = Ws[(k + 2) * 32 + lane];
            float w3 = Ws[(k + 3) * 32 + lane];
            uint2 u0 = *(const uint2*)(x0 + k);
            uint2 u1 = *(const uint2*)(x1 + k);
            uint2 u2 = *(const uint2*)(x2 + k);
            uint2 u3 = *(const uint2*)(x3 + k);
            float2 p00 = __bfloat1622float2(*(__nv_bfloat162*)&u0.x);
            float2 p01 = __bfloat1622float2(*(__nv_bfloat162*)&u0.y);
            float2 p10 = __bfloat1622float2(*(__nv_bfloat162*)&u1.x);
            float2 p11 = __bfloat1622float2(*(__nv_bfloat162*)&u1.y);
            float2 p20 = __bfloat1622float2(*(__nv_bfloat162*)&u2.x);
            float2 p21 = __bfloat1622float2(*(__nv_bfloat162*)&u2.y);
            float2 p30 = __bfloat1622float2(*(__nv_bfloat162*)&u3.x);
            float2 p31 = __bfloat1622float2(*(__nv_bfloat162*)&u3.y);
            a0 += p00.x * w0 + p00.y * w1 + p01.x * w2 + p01.y * w3;
            a1 += p10.x * w0 + p10.y * w1 + p11.x * w2 + p11.y * w3;
            a2 += p20.x * w0 + p20.y * w1 + p21.x * w2 + p21.y * w3;
            a3 += p30.x * w0 + p30.y * w1 + p31.x * w2 + p31.y * w3;
        }
        if (lane < DSTATE) {
            a0 = (a0 > 20.f) ? a0 : log1pf(__expf(a0));
            a1 = (a1 > 20.f) ? a1 : log1pf(__expf(a1));
            a2 = (a2 > 20.f) ? a2 : log1pf(__expf(a2));
            a3 = (a3 > 20.f) ? a3 : log1pf(__expf(a3));
        }
        g_ssm[(size_t)(tok + 0) * 32 + lane] = a0;
        g_ssm[(size_t)(tok + 1) * 32 + lane] = a1;
        g_ssm[(size_t)(tok + 2) * 32 + lane] = a2;
        g_ssm[(size_t)(tok + 3) * 32 + lane] = a3;
    }
}

// ---------------- selective scan: cp.async chunked SMEM pipeline ----------------
// Chunk = 18 steps; 50 chunks = 900. Stage: ssm 2304B | xs 4608B | res 4608B = 11520B, x2.
#define SCH 18
#define SST 11520

__device__ __forceinline__ void scan_stage(uint32_t dst, int b, int d0, int t0, int tid)
{
    const char* ssrc = (const char*)(g_ssm + (size_t)(b * SEQ + t0) * 32);
#pragma unroll 2
    for (int i = tid; i < 144; i += 128)
        CP_ASYNC16(dst + i * 16, ssrc + i * 16);
#pragma unroll 3
    for (int i = tid; i < 288; i += 128) {
        int r = i >> 4, o = (i & 15) << 4;
        CP_ASYNC16(dst + 2304 + r * 256 + o,
                   (const char*)(g_xs + (size_t)(b * SEQ + t0 + r) * DINNER + d0) + o);
    }
#pragma unroll 3
    for (int i = tid; i < 288; i += 128) {
        int r = i >> 4, o = (i & 15) << 4;
        CP_ASYNC16(dst + 6912 + r * 256 + o,
                   (const char*)(g_xz + (size_t)(b * SEQ + t0 + r) * 2 * DINNER + DINNER + d0) + o);
    }
}

__global__ __launch_bounds__(128) void scan_kernel(const float* __restrict__ A_log,
                                                   const float* __restrict__ Dp, int l)
{
    extern __shared__ char ssm_smem[];
    uint32_t sb = smem_u32(ssm_smem);
    int tid = threadIdx.x;
    int b   = blockIdx.x;
    int d0  = blockIdx.y * 128;
    int d   = d0 + tid;

    const float* Al = A_log + (size_t)(l * DINNER + d) * DSTATE;
    float a2[DSTATE];
#pragma unroll
    for (int n = 0; n < DSTATE; n++) a2[n] = -__expf(Al[n]) * LOG2E;
    float Dv = Dp[l * DINNER + d];
    float h[DSTATE];
#pragma unroll
    for (int n = 0; n < DSTATE; n++) h[n] = 0.f;

    scan_stage(sb, b, d0, 0, tid);           CP_COMMIT();
    scan_stage(sb + SST, b, d0, SCH, tid);   CP_COMMIT();

    int tok0 = b * SEQ;
    for (int c = 0; c < 50; c++) {
        CP_WAIT1();
        __syncthreads();
        int st = (c & 1);
        const float* ssp = (const float*)(ssm_smem + st * SST);
        const __nv_bfloat16* xsp = (const __nv_bfloat16*)(ssm_smem + st * SST + 2304);
        const __nv_bfloat16* rsp = (const __nv_bfloat16*)(ssm_smem + st * SST + 6912);
        __nv_bfloat16* yp = g_yb + (size_t)(tok0 + c * SCH) * DINNER + d;

#pragma unroll 2
        for (int t = 0; t < SCH; t++) {
            const float4* sp = (const float4*)(ssp + t * 32);
            float4 d0v = sp[0], d1v = sp[1], d2v = sp[2], d3v = sp[3];
            float4 b0v = sp[4], b1v = sp[5], b2v = sp[6], b3v = sp[7];
            float dl[DSTATE] = {d0v.x,d0v.y,d0v.z,d0v.w, d1v.x,d1v.y,d1v.z,d1v.w,
                                d2v.x,d2v.y,d2v.z,d2v.w, d3v.x,d3v.y,d3v.z,d3v.w};
            float bm[DSTATE] = {b0v.x,b0v.y,b0v.z,b0v.w, b1v.x,b1v.y,b1v.z,b1v.w,
                                b2v.x,b2v.y,b2v.z,b2v.w, b3v.x,b3v.y,b3v.z,b3v.w};
            float xv = __bfloat162float(xsp[t * 128 + tid]);
            float rv = __bfloat162float(rsp[t * 128 + tid]);
            float accv = 0.f;
#pragma unroll
            for (int n = 0; n < DSTATE; n++) {
                float e = exp2f(a2[n] * dl[n]);
                h[n] = h[n] * e + xv * bm[n];
                accv += h[n] * bm[n];
            }
            float sl = rv * (1.f / (1.f + __expf(-rv)));
            yp[(size_t)t * DINNER] = __float2bfloat16((accv + Dv * xv) * sl);
        }
        __syncthreads();
        if (c + 2 < 50)
            scan_stage(sb + st * SST, b, d0, (c + 2) * SCH, tid);
        CP_COMMIT();
    }
}

// ---------------- residual add + layernorm (fp32 + bf16 mirror) ----------------
__global__ void add_ln_kernel(const float* __restrict__ gma,
                              const float* __restrict__ bta)
{
    int gw   = (blockIdx.x * blockDim.x + threadIdx.x) >> 5;
    int lane = threadIdx.x & 31;
    if (gw >= TOKENS) return;
    float* xr = g_x + (size_t)gw * DMODEL;
    __nv_bfloat16* xb = g_xb + (size_t)gw * DMODEL;
    const float* orow = g_o + (size_t)gw * DMODEL;

    float v[8];
    float sum = 0.f;
#pragma unroll
    for (int i = 0; i < 8; i++) {
        int c = lane + i * 32;
        v[i] = xr[c] + orow[c];
        sum += v[i];
    }
#pragma unroll
    for (int o = 16; o > 0; o >>= 1) sum += __shfl_xor_sync(0xFFFFFFFF, sum, o);
    float mu = sum * (1.f / DMODEL);
    float s2 = 0.f;
#pragma unroll
    for (int i = 0; i < 8; i++) { float dd = v[i] - mu; s2 += dd * dd; }
#pragma unroll
    for (int o = 16; o > 0; o >>= 1) s2 += __shfl_xor_sync(0xFFFFFFFF, s2, o);
    float rstd = rsqrtf(s2 * (1.f / DMODEL) + LN_EPS);
#pragma unroll
    for (int i = 0; i < 8; i++) {
        int c = lane + i * 32;
        float nv = (v[i] - mu) * rstd * gma[c] + bta[c];
        xr[c] = nv;
        xb[c] = __float2bfloat16(nv);
    }
}

// ---------------- heads ----------------
__global__ void heads_kernel(const float* __restrict__ c1w, const float* __restrict__ c1b,
                             const float* __restrict__ c2w, const float* __restrict__ c2b,
                             const float* __restrict__ q1w, const float* __restrict__ q1b,
                             const float* __restrict__ q2w, const float* __restrict__ q2b,
                             float* __restrict__ out)
{
    __shared__ float fin[DMODEL];
    __shared__ float hc[128], hq[128];
    int b = blockIdx.x, t = threadIdx.x;
    const float* f = g_x + (size_t)(b * SEQ + SEQ - 1) * DMODEL;
    fin[t] = f[t];
    fin[t + 128] = f[t + 128];
    __syncthreads();
    float a1 = c1b[t], a2 = q1b[t];
#pragma unroll 4
    for (int k = 0; k < DMODEL; k++) {
        float fv = fin[k];
        a1 += fv * c1w[k * 128 + t];
        a2 += fv * q1w[k * 128 + t];
    }
    hc[t] = fmaxf(a1, 0.f);
    hq[t] = fmaxf(a2, 0.f);
    __syncthreads();
    if (t == 0) {
        float s = c2b[0];
        for (int k = 0; k < 128; k++) s += hc[k] * c2w[k];
        out[b] = fmaxf(s, 0.f);
    }
    if (t < 10) {
        float s = q2b[t];
        for (int k = 0; k < 128; k++) s += hq[k] * q2w[k * 10 + t];
        out[BATCH + b * 10 + t] = fmaxf(s, 0.f);
    }
}

// ---------------- launch ----------------
extern "C" void kernel_launch(void* const* d_in, const int* in_sizes, int n_in,
                              void* d_out, int out_size)
{
    const int*   grid   = (const int*)  d_in[0];
    const float* ce     = (const float*)d_in[1];
    const float* pe     = (const float*)d_in[2];
    const float* in_w   = (const float*)d_in[3];
    const float* in_b   = (const float*)d_in[4];
    const float* conv_w = (const float*)d_in[5];
    const float* conv_b = (const float*)d_in[6];
    const float* xp_w   = (const float*)d_in[7];
    const float* xp_b   = (const float*)d_in[8];
    const float* A_log  = (const float*)d_in[9];
    const float* Dp     = (const float*)d_in[10];
    const float* out_w  = (const float*)d_in[11];
    const float* out_b  = (const float*)d_in[12];
    const float* ln_g   = (const float*)d_in[13];
    const float* ln_b   = (const float*)d_in[14];
    const float* c1w    = (const float*)d_in[15];
    const float* c1b    = (const float*)d_in[16];
    const float* c2w    = (const float*)d_in[17];
    const float* c2b    = (const float*)d_in[18];
    const float* q1w    = (const float*)d_in[19];
    const float* q1b    = (const float*)d_in[20];
    const float* q2w    = (const float*)d_in[21];
    const float* q2b    = (const float*)d_in[22];
    float* out = (float*)d_out;

    __nv_bfloat16 *pxb, *pyb, *pxz;
    uint32_t *pwbi, *pwbo;
    float *po;
    cudaGetSymbolAddress((void**)&pxb,  g_xb);
    cudaGetSymbolAddress((void**)&pyb,  g_yb);
    cudaGetSymbolAddress((void**)&pxz,  g_xz);
    cudaGetSymbolAddress((void**)&po,   g_o);
    cudaGetSymbolAddress((void**)&pwbi, g_wbi);
    cudaGetSymbolAddress((void**)&pwbo, g_wbo);

    cudaFuncSetAttribute(xproj_kernel, cudaFuncAttributeMaxDynamicSharedMemorySize,
                         DINNER * 32 * (int)sizeof(float));
    cudaFuncSetAttribute(gemm_bf16_kernel<0>, cudaFuncAttributeMaxDynamicSharedMemorySize, GSM_TOTAL);
    cudaFuncSetAttribute(gemm_bf16_kernel<1>, cudaFuncAttributeMaxDynamicSharedMemorySize, GSM_TOTAL);

    // 2 convert launches (launches 1-2)
    {
        int nA = NLAYERS * 2 * DINNER * (DMODEL / 2);
        convert_in_w_kernel<<<(nA + 255) / 256, 256>>>(in_w, pwbi);
        int nB = NLAYERS * DMODEL * (DINNER / 2);
        convert_out_w_kernel<<<(nB + 255) / 256, 256>>>(out_w, pwbo);
    }
    // embed (launch 3)
    {
        int n = TOKENS * (DMODEL / 4);
        embed_kernel<<<(n + 255) / 256, 256>>>(grid, ce, pe);
    }

    for (int l = 0; l < NLAYERS; l++) {
        // in_proj (layer 0 = launch 4 → ncu capture)
        gemm_bf16_kernel<1><<<dim3(8, TOKENS / 128), 256, GSM_TOTAL>>>(
            pxb, (const __nv_bfloat16*)(pwbi + (size_t)l * 2 * DINNER * (DMODEL / 2)),
            in_b + l * 2 * DINNER, pxz, TOKENS, 2 * DINNER, DMODEL);

        {
            int n = TOKENS * (DINNER / 4);
            conv_silu_kernel<<<(n + 255) / 256, 256>>>(conv_w, conv_b, l);
        }

        xproj_kernel<<<TOKENS / 128, 256, DINNER * 32 * sizeof(float)>>>(xp_w, xp_b, l);

        scan_kernel<<<dim3(BATCH, DINNER / 128), 128, 2 * SST>>>(A_log, Dp, l);

        gemm_bf16_kernel<0><<<dim3(2, TOKENS / 128), 256, GSM_TOTAL>>>(
            pyb, (const __nv_bfloat16*)(pwbo + (size_t)l * DMODEL * (DINNER / 2)),
            out_b + l * DMODEL, po, TOKENS, DMODEL, DINNER);

        add_ln_kernel<<<(TOKENS * 32 + 255) / 256, 256>>>(ln_g, ln_b);
    }

    heads_kernel<<<BATCH, 128>>>(c1w, c1b, c2w, c2b, q1w, q1b, q2w, q2b, out);
}

// round 9
// speedup vs baseline: 5.0330x; 2.1221x over previous
#include <cuda_runtime.h>
#include <cuda_bf16.h>
#include <math.h>
#include <stdint.h>

#define NLAYERS 4
#define DMODEL  256
#define DINNER  512
#define DSTATE  16
#define DCONV   4
#define BATCH   64
#define SEQ     900
#define TOKENS  (BATCH * SEQ)   // 57600
#define LN_EPS  1e-5f
#define LOG2E   1.4426950408889634f

// ---------------- device scratch ----------------
__device__ float g_x  [TOKENS * DMODEL];
__device__ __nv_bfloat16 g_xb[TOKENS * DMODEL];
__device__ __nv_bfloat16 g_xz[TOKENS * 2 * DINNER];
__device__ __nv_bfloat16 g_xs[TOKENS * DINNER];
__device__ float g_ssm[TOKENS * 2 * DSTATE];
__device__ __nv_bfloat16 g_yb[TOKENS * DINNER];
__device__ float g_o  [TOKENS * DMODEL];
// K-major bf16 weights (bf16x2-packed u32)
__device__ uint32_t g_wbi[NLAYERS * 2 * DINNER * (DMODEL / 2)];
__device__ uint32_t g_wbo[NLAYERS * DMODEL * (DINNER / 2)];
__device__ uint32_t g_wbx[NLAYERS * 2 * DSTATE * (DINNER / 2)];

__device__ __forceinline__ uint32_t packbf(float lo, float hi) {
    uint32_t r;
    asm("cvt.rn.bf16x2.f32 %0, %1, %2;" : "=r"(r) : "f"(hi), "f"(lo));
    return r;
}
__device__ __forceinline__ uint32_t smem_u32(const void* p) {
    uint32_t a;
    asm("{ .reg .u64 t; cvta.to.shared.u64 t, %1; cvt.u32.u64 %0, t; }" : "=r"(a) : "l"(p));
    return a;
}
#define CP_ASYNC16(dst, src) \
    asm volatile("cp.async.cg.shared.global [%0], [%1], 16;" :: "r"(dst), "l"(src))
#define CP_COMMIT() asm volatile("cp.async.commit_group;" ::: "memory")
#define CP_WAIT1()  asm volatile("cp.async.wait_group 1;" ::: "memory")

// ---------------- weight converts ----------------
__global__ void convert_in_w_kernel(const float* __restrict__ w, uint32_t* __restrict__ wt)
{
    const int PER = 2 * DINNER * (DMODEL / 2);
    int idx = blockIdx.x * blockDim.x + threadIdx.x;
    if (idx >= NLAYERS * PER) return;
    int l  = idx / PER;
    int r  = idx % PER;
    int n  = r % (2 * DINNER);
    int k2 = r / (2 * DINNER);
    const float* wl = w + (size_t)l * DMODEL * 2 * DINNER;
    wt[(size_t)l * PER + (size_t)n * (DMODEL / 2) + k2] =
        packbf(wl[(size_t)(2 * k2) * 2 * DINNER + n], wl[(size_t)(2 * k2 + 1) * 2 * DINNER + n]);
}
__global__ void convert_out_w_kernel(const float* __restrict__ w, uint32_t* __restrict__ wt)
{
    const int PER = DMODEL * (DINNER / 2);
    int idx = blockIdx.x * blockDim.x + threadIdx.x;
    if (idx >= NLAYERS * PER) return;
    int l  = idx / PER;
    int r  = idx % PER;
    int n  = r % DMODEL;
    int k2 = r / DMODEL;
    const float* wl = w + (size_t)l * DINNER * DMODEL;
    wt[(size_t)l * PER + (size_t)n * (DINNER / 2) + k2] =
        packbf(wl[(size_t)(2 * k2) * DMODEL + n], wl[(size_t)(2 * k2 + 1) * DMODEL + n]);
}
__global__ void convert_xp_w_kernel(const float* __restrict__ w, uint32_t* __restrict__ wt)
{
    const int PER = 32 * (DINNER / 2);
    int idx = blockIdx.x * blockDim.x + threadIdx.x;
    if (idx >= NLAYERS * PER) return;
    int l  = idx / PER;
    int r  = idx % PER;
    int n  = r % 32;
    int k2 = r / 32;
    const float* wl = w + (size_t)l * DINNER * 32;
    wt[(size_t)l * PER + (size_t)n * (DINNER / 2) + k2] =
        packbf(wl[(size_t)(2 * k2) * 32 + n], wl[(size_t)(2 * k2 + 1) * 32 + n]);
}

// ---------------- embed ----------------
__global__ void embed_kernel(const int* __restrict__ grid,
                             const float* __restrict__ ce,
                             const float* __restrict__ pe)
{
    int idx = blockIdx.x * blockDim.x + threadIdx.x;
    if (idx >= TOKENS * (DMODEL / 4)) return;
    int tok = idx >> 6;
    int c4  = (idx & 63) * 4;
    int s   = tok % SEQ;
    int g   = grid[tok];
    float4 a = *(const float4*)&ce[g * DMODEL + c4];
    float4 p = *(const float4*)&pe[s * DMODEL + c4];
    float4 r; r.x = a.x + p.x; r.y = a.y + p.y; r.z = a.z + p.z; r.w = a.w + p.w;
    *(float4*)&g_x[tok * DMODEL + c4] = r;
    *(uint2*)&g_xb[tok * DMODEL + c4] = make_uint2(packbf(r.x, r.y), packbf(r.z, r.w));
}

// ---------------- bf16 GEMM: 128xNT tile, GBK=64, 3-stage cp.async + ldmatrix ----------------
// MODE 0: fp32 out. MODE 1: bf16 out. MODE 2: fp32 out + softplus on cols<16 (xproj).
#define ABYTES 18432            // 128 rows * 144B

template<int NT>
__device__ __forceinline__ void gemm_stage64(uint32_t st,
                                             const __nv_bfloat16* __restrict__ A,
                                             const __nv_bfloat16* __restrict__ Bw,
                                             int row0, int col0, int K, int k0, int tid)
{
#pragma unroll
    for (int p = 0; p < 4; p++) {
        int i = tid + p * 256;
        int r = i >> 3, cc = (i & 7) << 4;
        CP_ASYNC16(st + r * 144 + cc, (const char*)(A + (size_t)(row0 + r) * K + k0) + cc);
    }
#pragma unroll
    for (int p = 0; p < NT / 32; p++) {
        int i = tid + p * 256;
        int r = i >> 3, cc = (i & 7) << 4;
        CP_ASYNC16(st + ABYTES + r * 144 + cc, (const char*)(Bw + (size_t)(col0 + r) * K + k0) + cc);
    }
}

template<int NT, int MODE>
__global__ __launch_bounds__(256, 2) void gemm_bf16_kernel(
    const __nv_bfloat16* __restrict__ A, const __nv_bfloat16* __restrict__ Bw,
    const float* __restrict__ bias, void* __restrict__ Cv,
    int M, int N, int K)
{
    constexpr int WMI = (NT == 128) ? 4 : 1;
    constexpr int SSTAGE = (128 + NT) * 144;

    extern __shared__ char smem[];
    uint32_t sb = smem_u32(smem);

    int tid  = threadIdx.x;
    int lane = tid & 31;
    int warp = tid >> 5;
    int wm   = (NT == 128) ? (warp >> 2) : warp;
    int wn   = (NT == 128) ? (warp & 3) : 0;
    int row0 = blockIdx.y * 128;
    int col0 = blockIdx.x * NT;
    int grp  = lane >> 2;
    int qid  = lane & 3;

    float acc[WMI][4][4];
#pragma unroll
    for (int i = 0; i < WMI; i++)
#pragma unroll
        for (int j = 0; j < 4; j++)
#pragma unroll
            for (int r = 0; r < 4; r++) acc[i][j][r] = 0.f;

    int NC = K / 64;
    gemm_stage64<NT>(sb, A, Bw, row0, col0, K, 0, tid);            CP_COMMIT();
    gemm_stage64<NT>(sb + SSTAGE, A, Bw, row0, col0, K, 64, tid);  CP_COMMIT();

    int a_row  = wm * (WMI * 16) + (lane & 15);
    int a_koff = (lane >> 4) << 4;
    int b_row0 = wn * 32 + ((lane >> 4) << 3) + (lane & 7);
    int b_koff = ((lane >> 3) & 1) << 4;

    for (int c = 0; c < NC; c++) {
        CP_WAIT1();
        __syncthreads();
        if (c + 2 < NC) {
            gemm_stage64<NT>(sb + ((c + 2) % 3) * SSTAGE, A, Bw, row0, col0, K, (c + 2) * 64, tid);
            CP_COMMIT();
        }
        uint32_t stA = sb + (c % 3) * SSTAGE;
        uint32_t stB = stA + ABYTES;
#pragma unroll
        for (int ks = 0; ks < 4; ks++) {
            uint32_t af[WMI][4];
#pragma unroll
            for (int i = 0; i < WMI; i++) {
                uint32_t addr = stA + (a_row + i * 16) * 144 + ks * 32 + a_koff;
                asm volatile("ldmatrix.sync.aligned.m8n8.x4.shared.b16 {%0,%1,%2,%3}, [%4];"
                             : "=r"(af[i][0]), "=r"(af[i][1]), "=r"(af[i][2]), "=r"(af[i][3])
                             : "r"(addr));
            }
            uint32_t bf_[2][4];
#pragma unroll
            for (int jj = 0; jj < 2; jj++) {
                uint32_t addr = stB + (b_row0 + jj * 16) * 144 + ks * 32 + b_koff;
                asm volatile("ldmatrix.sync.aligned.m8n8.x4.shared.b16 {%0,%1,%2,%3}, [%4];"
                             : "=r"(bf_[jj][0]), "=r"(bf_[jj][1]), "=r"(bf_[jj][2]), "=r"(bf_[jj][3])
                             : "r"(addr));
            }
#pragma unroll
            for (int i = 0; i < WMI; i++)
#pragma unroll
                for (int j = 0; j < 4; j++) {
                    asm volatile(
                        "mma.sync.aligned.m16n8k16.row.col.f32.bf16.bf16.f32 "
                        "{%0,%1,%2,%3}, {%4,%5,%6,%7}, {%8,%9}, {%0,%1,%2,%3};"
                        : "+f"(acc[i][j][0]), "+f"(acc[i][j][1]),
                          "+f"(acc[i][j][2]), "+f"(acc[i][j][3])
                        : "r"(af[i][0]), "r"(af[i][1]), "r"(af[i][2]), "r"(af[i][3]),
                          "r"(bf_[j >> 1][(j & 1) * 2]), "r"(bf_[j >> 1][(j & 1) * 2 + 1]));
                }
        }
        __syncthreads();
    }

#pragma unroll
    for (int i = 0; i < WMI; i++) {
        int rg0 = row0 + wm * (WMI * 16) + i * 16 + grp;
#pragma unroll
        for (int j = 0; j < 4; j++) {
            int cg = col0 + wn * 32 + j * 8 + qid * 2;
            float b0 = bias[cg], b1 = bias[cg + 1];
            float v00 = acc[i][j][0] + b0, v01 = acc[i][j][1] + b1;
            float v10 = acc[i][j][2] + b0, v11 = acc[i][j][3] + b1;
            if (MODE == 2 && j < 2) {   // softplus on delta columns (<16)
                v00 = (v00 > 20.f) ? v00 : log1pf(__expf(v00));
                v01 = (v01 > 20.f) ? v01 : log1pf(__expf(v01));
                v10 = (v10 > 20.f) ? v10 : log1pf(__expf(v10));
                v11 = (v11 > 20.f) ? v11 : log1pf(__expf(v11));
            }
            if (MODE == 1) {
                __nv_bfloat16* Cb = (__nv_bfloat16*)Cv;
                *(uint32_t*)&Cb[(size_t)rg0 * N + cg]       = packbf(v00, v01);
                *(uint32_t*)&Cb[(size_t)(rg0 + 8) * N + cg] = packbf(v10, v11);
            } else {
                float* C = (float*)Cv;
                *(float2*)&C[(size_t)rg0 * N + cg]       = make_float2(v00, v01);
                *(float2*)&C[(size_t)(rg0 + 8) * N + cg] = make_float2(v10, v11);
            }
        }
    }
}

// ---------------- depthwise causal conv(4) + silu, 4 tokens/thread sliding window ----------------
__global__ void conv_silu_kernel(const float* __restrict__ cw,
                                 const float* __restrict__ cb, int l)
{
    int idx = blockIdx.x * blockDim.x + threadIdx.x;   // (TOKENS/4) * 128
    if (idx >= (TOKENS / 4) * 128) return;
    int g128 = idx & 127;
    int q    = idx >> 7;
    int t0   = q * 4;
    int b    = t0 / SEQ;
    int s0   = t0 % SEQ;
    int c    = g128 * 4;

    float4 w0 = *(const float4*)&cw[(l * DINNER + c + 0) * DCONV];
    float4 w1 = *(const float4*)&cw[(l * DINNER + c + 1) * DCONV];
    float4 w2 = *(const float4*)&cw[(l * DINNER + c + 2) * DCONV];
    float4 w3 = *(const float4*)&cw[(l * DINNER + c + 3) * DCONV];
    float wa[4][4] = {{w0.x,w0.y,w0.z,w0.w},{w1.x,w1.y,w1.z,w1.w},
                      {w2.x,w2.y,w2.z,w2.w},{w3.x,w3.y,w3.z,w3.w}};
    float bs0 = cb[l * DINNER + c + 0];
    float bs1 = cb[l * DINNER + c + 1];
    float bs2 = cb[l * DINNER + c + 2];
    float bs3 = cb[l * DINNER + c + 3];

    float rowv[7][4];
#pragma unroll
    for (int k = 0; k < 7; k++) {
        int s = s0 - 3 + k;
        if (s >= 0) {
            uint2 v = *(const uint2*)&g_xz[(size_t)(b * SEQ + s) * 2 * DINNER + c];
            float2 p0 = __bfloat1622float2(*(__nv_bfloat162*)&v.x);
            float2 p1 = __bfloat1622float2(*(__nv_bfloat162*)&v.y);
            rowv[k][0] = p0.x; rowv[k][1] = p0.y; rowv[k][2] = p1.x; rowv[k][3] = p1.y;
        } else {
            rowv[k][0] = rowv[k][1] = rowv[k][2] = rowv[k][3] = 0.f;
        }
    }
#pragma unroll
    for (int t = 0; t < 4; t++) {
        float o0 = bs0, o1 = bs1, o2 = bs2, o3 = bs3;
#pragma unroll
        for (int k = 0; k < DCONV; k++) {
            o0 += rowv[t + k][0] * wa[0][k];
            o1 += rowv[t + k][1] * wa[1][k];
            o2 += rowv[t + k][2] * wa[2][k];
            o3 += rowv[t + k][3] * wa[3][k];
        }
        o0 = o0 * (1.f / (1.f + __expf(-o0)));
        o1 = o1 * (1.f / (1.f + __expf(-o1)));
        o2 = o2 * (1.f / (1.f + __expf(-o2)));
        o3 = o3 * (1.f / (1.f + __expf(-o3)));
        *(uint2*)&g_xs[(size_t)(b * SEQ + s0 + t) * DINNER + c] =
            make_uint2(packbf(o0, o1), packbf(o2, o3));
    }
}

// ---------------- selective scan: cp.async chunked SMEM pipeline ----------------
#define SCH 18
#define SST 11520

__device__ __forceinline__ void scan_stage(uint32_t dst, int b, int d0, int t0, int tid)
{
    const char* ssrc = (const char*)(g_ssm + (size_t)(b * SEQ + t0) * 32);
#pragma unroll 2
    for (int i = tid; i < 144; i += 128)
        CP_ASYNC16(dst + i * 16, ssrc + i * 16);
#pragma unroll 3
    for (int i = tid; i < 288; i += 128) {
        int r = i >> 4, o = (i & 15) << 4;
        CP_ASYNC16(dst + 2304 + r * 256 + o,
                   (const char*)(g_xs + (size_t)(b * SEQ + t0 + r) * DINNER + d0) + o);
    }
#pragma unroll 3
    for (int i = tid; i < 288; i += 128) {
        int r = i >> 4, o = (i & 15) << 4;
        CP_ASYNC16(dst + 6912 + r * 256 + o,
                   (const char*)(g_xz + (size_t)(b * SEQ + t0 + r) * 2 * DINNER + DINNER + d0) + o);
    }
}

__global__ __launch_bounds__(128) void scan_kernel(const float* __restrict__ A_log,
                                                   const float* __restrict__ Dp, int l)
{
    extern __shared__ char ssm_smem[];
    uint32_t sb = smem_u32(ssm_smem);
    int tid = threadIdx.x;
    int b   = blockIdx.x;
    int d0  = blockIdx.y * 128;
    int d   = d0 + tid;

    const float* Al = A_log + (size_t)(l * DINNER + d) * DSTATE;
    float a2[DSTATE];
#pragma unroll
    for (int n = 0; n < DSTATE; n++) a2[n] = -__expf(Al[n]) * LOG2E;
    float Dv = Dp[l * DINNER + d];
    float h[DSTATE];
#pragma unroll
    for (int n = 0; n < DSTATE; n++) h[n] = 0.f;

    scan_stage(sb, b, d0, 0, tid);           CP_COMMIT();
    scan_stage(sb + SST, b, d0, SCH, tid);   CP_COMMIT();

    int tok0 = b * SEQ;
    for (int c = 0; c < 50; c++) {
        CP_WAIT1();
        __syncthreads();
        int st = (c & 1);
        const float* ssp = (const float*)(ssm_smem + st * SST);
        const __nv_bfloat16* xsp = (const __nv_bfloat16*)(ssm_smem + st * SST + 2304);
        const __nv_bfloat16* rsp = (const __nv_bfloat16*)(ssm_smem + st * SST + 6912);
        __nv_bfloat16* yp = g_yb + (size_t)(tok0 + c * SCH) * DINNER + d;

#pragma unroll 2
        for (int t = 0; t < SCH; t++) {
            const float4* sp = (const float4*)(ssp + t * 32);
            float4 d0v = sp[0], d1v = sp[1], d2v = sp[2], d3v = sp[3];
            float4 b0v = sp[4], b1v = sp[5], b2v = sp[6], b3v = sp[7];
            float dl[DSTATE] = {d0v.x,d0v.y,d0v.z,d0v.w, d1v.x,d1v.y,d1v.z,d1v.w,
                                d2v.x,d2v.y,d2v.z,d2v.w, d3v.x,d3v.y,d3v.z,d3v.w};
            float bm[DSTATE] = {b0v.x,b0v.y,b0v.z,b0v.w, b1v.x,b1v.y,b1v.z,b1v.w,
                                b2v.x,b2v.y,b2v.z,b2v.w, b3v.x,b3v.y,b3v.z,b3v.w};
            float xv = __bfloat162float(xsp[t * 128 + tid]);
            float rv = __bfloat162float(rsp[t * 128 + tid]);
            float accv = 0.f;
#pragma unroll
            for (int n = 0; n < DSTATE; n++) {
                float e = exp2f(a2[n] * dl[n]);
                h[n] = h[n] * e + xv * bm[n];
                accv += h[n] * bm[n];
            }
            float sl = rv * (1.f / (1.f + __expf(-rv)));
            yp[(size_t)t * DINNER] = __float2bfloat16((accv + Dv * xv) * sl);
        }
        __syncthreads();
        if (c + 2 < 50)
            scan_stage(sb + st * SST, b, d0, (c + 2) * SCH, tid);
        CP_COMMIT();
    }
}

// ---------------- residual add + layernorm ----------------
__global__ void add_ln_kernel(const float* __restrict__ gma,
                              const float* __restrict__ bta)
{
    int gw   = (blockIdx.x * blockDim.x + threadIdx.x) >> 5;
    int lane = threadIdx.x & 31;
    if (gw >= TOKENS) return;
    float* xr = g_x + (size_t)gw * DMODEL;
    __nv_bfloat16* xb = g_xb + (size_t)gw * DMODEL;
    const float* orow = g_o + (size_t)gw * DMODEL;

    float v[8];
    float sum = 0.f;
#pragma unroll
    for (int i = 0; i < 8; i++) {
        int c = lane + i * 32;
        v[i] = xr[c] + orow[c];
        sum += v[i];
    }
#pragma unroll
    for (int o = 16; o > 0; o >>= 1) sum += __shfl_xor_sync(0xFFFFFFFF, sum, o);
    float mu = sum * (1.f / DMODEL);
    float s2 = 0.f;
#pragma unroll
    for (int i = 0; i < 8; i++) { float dd = v[i] - mu; s2 += dd * dd; }
#pragma unroll
    for (int o = 16; o > 0; o >>= 1) s2 += __shfl_xor_sync(0xFFFFFFFF, s2, o);
    float rstd = rsqrtf(s2 * (1.f / DMODEL) + LN_EPS);
#pragma unroll
    for (int i = 0; i < 8; i++) {
        int c = lane + i * 32;
        float nv = (v[i] - mu) * rstd * gma[c] + bta[c];
        xr[c] = nv;
        xb[c] = __float2bfloat16(nv);
    }
}

// ---------------- heads ----------------
__global__ void heads_kernel(const float* __restrict__ c1w, const float* __restrict__ c1b,
                             const float* __restrict__ c2w, const float* __restrict__ c2b,
                             const float* __restrict__ q1w, const float* __restrict__ q1b,
                             const float* __restrict__ q2w, const float* __restrict__ q2b,
                             float* __restrict__ out)
{
    __shared__ float fin[DMODEL];
    __shared__ float hc[128], hq[128];
    int b = blockIdx.x, t = threadIdx.x;
    const float* f = g_x + (size_t)(b * SEQ + SEQ - 1) * DMODEL;
    fin[t] = f[t];
    fin[t + 128] = f[t + 128];
    __syncthreads();
    float a1 = c1b[t], a2 = q1b[t];
#pragma unroll 4
    for (int k = 0; k < DMODEL; k++) {
        float fv = fin[k];
        a1 += fv * c1w[k * 128 + t];
        a2 += fv * q1w[k * 128 + t];
    }
    hc[t] = fmaxf(a1, 0.f);
    hq[t] = fmaxf(a2, 0.f);
    __syncthreads();
    if (t == 0) {
        float s = c2b[0];
        for (int k = 0; k < 128; k++) s += hc[k] * c2w[k];
        out[b] = fmaxf(s, 0.f);
    }
    if (t < 10) {
        float s = q2b[t];
        for (int k = 0; k < 128; k++) s += hq[k] * q2w[k * 10 + t];
        out[BATCH + b * 10 + t] = fmaxf(s, 0.f);
    }
}

// ---------------- launch ----------------
extern "C" void kernel_launch(void* const* d_in, const int* in_sizes, int n_in,
                              void* d_out, int out_size)
{
    const int*   grid   = (const int*)  d_in[0];
    const float* ce     = (const float*)d_in[1];
    const float* pe     = (const float*)d_in[2];
    const float* in_w   = (const float*)d_in[3];
    const float* in_b   = (const float*)d_in[4];
    const float* conv_w = (const float*)d_in[5];
    const float* conv_b = (const float*)d_in[6];
    const float* xp_w   = (const float*)d_in[7];
    const float* xp_b   = (const float*)d_in[8];
    const float* A_log  = (const float*)d_in[9];
    const float* Dp     = (const float*)d_in[10];
    const float* out_w  = (const float*)d_in[11];
    const float* out_b  = (const float*)d_in[12];
    const float* ln_g   = (const float*)d_in[13];
    const float* ln_b   = (const float*)d_in[14];
    const float* c1w    = (const float*)d_in[15];
    const float* c1b    = (const float*)d_in[16];
    const float* c2w    = (const float*)d_in[17];
    const float* c2b    = (const float*)d_in[18];
    const float* q1w    = (const float*)d_in[19];
    const float* q1b    = (const float*)d_in[20];
    const float* q2w    = (const float*)d_in[21];
    const float* q2b    = (const float*)d_in[22];
    float* out = (float*)d_out;

    __nv_bfloat16 *pxb, *pyb, *pxz, *pxs;
    uint32_t *pwbi, *pwbo, *pwbx;
    float *po, *pssm;
    cudaGetSymbolAddress((void**)&pxb,  g_xb);
    cudaGetSymbolAddress((void**)&pyb,  g_yb);
    cudaGetSymbolAddress((void**)&pxz,  g_xz);
    cudaGetSymbolAddress((void**)&pxs,  g_xs);
    cudaGetSymbolAddress((void**)&po,   g_o);
    cudaGetSymbolAddress((void**)&pssm, g_ssm);
    cudaGetSymbolAddress((void**)&pwbi, g_wbi);
    cudaGetSymbolAddress((void**)&pwbo, g_wbo);
    cudaGetSymbolAddress((void**)&pwbx, g_wbx);

    const int SM128 = 3 * (128 + 128) * 144;   // 110592
    const int SM32  = 3 * (128 + 32) * 144;    // 69120
    cudaFuncSetAttribute(gemm_bf16_kernel<128, 0>, cudaFuncAttributeMaxDynamicSharedMemorySize, SM128);
    cudaFuncSetAttribute(gemm_bf16_kernel<128, 1>, cudaFuncAttributeMaxDynamicSharedMemorySize, SM128);
    cudaFuncSetAttribute(gemm_bf16_kernel<32, 2>,  cudaFuncAttributeMaxDynamicSharedMemorySize, SM32);

    // converts (3) + embed (1)
    {
        int nA = NLAYERS * 2 * DINNER * (DMODEL / 2);
        convert_in_w_kernel<<<(nA + 255) / 256, 256>>>(in_w, pwbi);
        int nB = NLAYERS * DMODEL * (DINNER / 2);
        convert_out_w_kernel<<<(nB + 255) / 256, 256>>>(out_w, pwbo);
        int nX = NLAYERS * 32 * (DINNER / 2);
        convert_xp_w_kernel<<<(nX + 255) / 256, 256>>>(xp_w, pwbx);
        int n = TOKENS * (DMODEL / 4);
        embed_kernel<<<(n + 255) / 256, 256>>>(grid, ce, pe);
    }

    for (int l = 0; l < NLAYERS; l++) {
        // in_proj: (T x 256) @ -> 1024, bf16 out
        gemm_bf16_kernel<128, 1><<<dim3(8, TOKENS / 128), 256, SM128>>>(
            pxb, (const __nv_bfloat16*)(pwbi + (size_t)l * 2 * DINNER * (DMODEL / 2)),
            in_b + l * 2 * DINNER, pxz, TOKENS, 2 * DINNER, DMODEL);

        {
            int n = (TOKENS / 4) * 128;
            conv_silu_kernel<<<(n + 255) / 256, 256>>>(conv_w, conv_b, l);
        }

        // xproj on tensor cores: (T x 512) -> 32, softplus fused
        gemm_bf16_kernel<32, 2><<<dim3(1, TOKENS / 128), 256, SM32>>>(
            pxs, (const __nv_bfloat16*)(pwbx + (size_t)l * 32 * (DINNER / 2)),
            xp_b + l * 32, pssm, TOKENS, 32, DINNER);

        scan_kernel<<<dim3(BATCH, DINNER / 128), 128, 2 * SST>>>(A_log, Dp, l);

        // out_proj: (T x 512) -> 256, fp32 out
        gemm_bf16_kernel<128, 0><<<dim3(2, TOKENS / 128), 256, SM128>>>(
            pyb, (const __nv_bfloat16*)(pwbo + (size_t)l * DMODEL * (DINNER / 2)),
            out_b + l * DMODEL, po, TOKENS, DMODEL, DINNER);

        add_ln_kernel<<<(TOKENS * 32 + 255) / 256, 256>>>(ln_g, ln_b);
    }

    heads_kernel<<<BATCH, 128>>>(c1w, c1b, c2w, c2b, q1w, q1b, q2w, q2b, out);
}

// round 10
// speedup vs baseline: 5.2516x; 1.0434x over previous
#include <cuda_runtime.h>
#include <cuda_bf16.h>
#include <math.h>
#include <stdint.h>

#define NLAYERS 4
#define DMODEL  256
#define DINNER  512
#define DSTATE  16
#define DCONV   4
#define BATCH   64
#define SEQ     900
#define TOKENS  (BATCH * SEQ)   // 57600
#define LN_EPS  1e-5f
#define LOG2E   1.4426950408889634f

// ---------------- device scratch ----------------
__device__ float g_x  [TOKENS * DMODEL];
__device__ __nv_bfloat16 g_xb[TOKENS * DMODEL];
__device__ __nv_bfloat16 g_xz[TOKENS * 2 * DINNER];
__device__ __nv_bfloat16 g_xs[TOKENS * DINNER];
__device__ float g_ssm[TOKENS * 2 * DSTATE];
__device__ __nv_bfloat16 g_yb[TOKENS * DINNER];
// K-major bf16 weights (bf16x2-packed u32)
__device__ uint32_t g_wbi[NLAYERS * 2 * DINNER * (DMODEL / 2)];
__device__ uint32_t g_wbo[NLAYERS * DMODEL * (DINNER / 2)];
__device__ uint32_t g_wbx[NLAYERS * 2 * DSTATE * (DINNER / 2)];

__device__ __forceinline__ uint32_t packbf(float lo, float hi) {
    uint32_t r;
    asm("cvt.rn.bf16x2.f32 %0, %1, %2;" : "=r"(r) : "f"(hi), "f"(lo));
    return r;
}
__device__ __forceinline__ uint32_t smem_u32(const void* p) {
    uint32_t a;
    asm("{ .reg .u64 t; cvta.to.shared.u64 t, %1; cvt.u32.u64 %0, t; }" : "=r"(a) : "l"(p));
    return a;
}
#define CP_ASYNC16(dst, src) \
    asm volatile("cp.async.cg.shared.global [%0], [%1], 16;" :: "r"(dst), "l"(src))
#define CP_COMMIT() asm volatile("cp.async.commit_group;" ::: "memory")
#define CP_WAIT1()  asm volatile("cp.async.wait_group 1;" ::: "memory")

// ---------------- weight converts ----------------
__global__ void convert_in_w_kernel(const float* __restrict__ w, uint32_t* __restrict__ wt)
{
    const int PER = 2 * DINNER * (DMODEL / 2);
    int idx = blockIdx.x * blockDim.x + threadIdx.x;
    if (idx >= NLAYERS * PER) return;
    int l  = idx / PER;
    int r  = idx % PER;
    int n  = r % (2 * DINNER);
    int k2 = r / (2 * DINNER);
    const float* wl = w + (size_t)l * DMODEL * 2 * DINNER;
    wt[(size_t)l * PER + (size_t)n * (DMODEL / 2) + k2] =
        packbf(wl[(size_t)(2 * k2) * 2 * DINNER + n], wl[(size_t)(2 * k2 + 1) * 2 * DINNER + n]);
}
__global__ void convert_out_w_kernel(const float* __restrict__ w, uint32_t* __restrict__ wt)
{
    const int PER = DMODEL * (DINNER / 2);
    int idx = blockIdx.x * blockDim.x + threadIdx.x;
    if (idx >= NLAYERS * PER) return;
    int l  = idx / PER;
    int r  = idx % PER;
    int n  = r % DMODEL;
    int k2 = r / DMODEL;
    const float* wl = w + (size_t)l * DINNER * DMODEL;
    wt[(size_t)l * PER + (size_t)n * (DINNER / 2) + k2] =
        packbf(wl[(size_t)(2 * k2) * DMODEL + n], wl[(size_t)(2 * k2 + 1) * DMODEL + n]);
}
__global__ void convert_xp_w_kernel(const float* __restrict__ w, uint32_t* __restrict__ wt)
{
    const int PER = 32 * (DINNER / 2);
    int idx = blockIdx.x * blockDim.x + threadIdx.x;
    if (idx >= NLAYERS * PER) return;
    int l  = idx / PER;
    int r  = idx % PER;
    int n  = r % 32;
    int k2 = r / 32;
    const float* wl = w + (size_t)l * DINNER * 32;
    wt[(size_t)l * PER + (size_t)n * (DINNER / 2) + k2] =
        packbf(wl[(size_t)(2 * k2) * 32 + n], wl[(size_t)(2 * k2 + 1) * 32 + n]);
}

// ---------------- embed ----------------
__global__ void embed_kernel(const int* __restrict__ grid,
                             const float* __restrict__ ce,
                             const float* __restrict__ pe)
{
    int idx = blockIdx.x * blockDim.x + threadIdx.x;
    if (idx >= TOKENS * (DMODEL / 4)) return;
    int tok = idx >> 6;
    int c4  = (idx & 63) * 4;
    int s   = tok % SEQ;
    int g   = grid[tok];
    float4 a = *(const float4*)&ce[g * DMODEL + c4];
    float4 p = *(const float4*)&pe[s * DMODEL + c4];
    float4 r; r.x = a.x + p.x; r.y = a.y + p.y; r.z = a.z + p.z; r.w = a.w + p.w;
    *(float4*)&g_x[tok * DMODEL + c4] = r;
    *(uint2*)&g_xb[tok * DMODEL + c4] = make_uint2(packbf(r.x, r.y), packbf(r.z, r.w));
}

// ---------------- bf16 GEMM: 128xNT tile, GBK=64, 3-stage cp.async + ldmatrix ----------------
// MODE 0: fp32 out. MODE 1: bf16 out. MODE 2: fp32 + softplus cols<16 (xproj).
// MODE 3: fused out_proj epilogue: bias + residual(g_x) + LayerNorm -> g_x fp32 + mirror bf16.
#define ABYTES 18432            // 128 rows * 144B

template<int NT>
__device__ __forceinline__ void gemm_stage64(uint32_t st,
                                             const __nv_bfloat16* __restrict__ A,
                                             const __nv_bfloat16* __restrict__ Bw,
                                             int row0, int col0, int K, int k0, int tid)
{
#pragma unroll
    for (int p = 0; p < 4; p++) {
        int i = tid + p * 256;
        int r = i >> 3, cc = (i & 7) << 4;
        CP_ASYNC16(st + r * 144 + cc, (const char*)(A + (size_t)(row0 + r) * K + k0) + cc);
    }
#pragma unroll
    for (int p = 0; p < NT / 32; p++) {
        int i = tid + p * 256;
        int r = i >> 3, cc = (i & 7) << 4;
        CP_ASYNC16(st + ABYTES + r * 144 + cc, (const char*)(Bw + (size_t)(col0 + r) * K + k0) + cc);
    }
}

template<int NT, int MODE>
__global__ __launch_bounds__(256, (NT == 256) ? 1 : 2) void gemm_bf16_kernel(
    const __nv_bfloat16* __restrict__ A, const __nv_bfloat16* __restrict__ Bw,
    const float* __restrict__ bias, void* __restrict__ Cv,
    int M, int N, int K,
    const float* __restrict__ gam, const float* __restrict__ bet,
    __nv_bfloat16* __restrict__ mirror)
{
    constexpr int WMI    = (NT >= 128) ? 4 : 1;
    constexpr int WNJ    = (NT == 256) ? 8 : 4;
    constexpr int WNSPAN = (NT == 256) ? 64 : 32;
    constexpr int NBJJ   = WNSPAN / 16;            // ldmatrix.x4 B loads per ks
    constexpr int SSTAGE = (128 + NT) * 144;

    extern __shared__ char smem[];
    uint32_t sb = smem_u32(smem);

    int tid  = threadIdx.x;
    int lane = tid & 31;
    int warp = tid >> 5;
    int wm   = (NT >= 128) ? (warp >> 2) : warp;
    int wn   = (NT >= 128) ? (warp & 3) : 0;
    int row0 = blockIdx.y * 128;
    int col0 = blockIdx.x * NT;
    int grp  = lane >> 2;
    int qid  = lane & 3;

    float acc[WMI][WNJ][4];
#pragma unroll
    for (int i = 0; i < WMI; i++)
#pragma unroll
        for (int j = 0; j < WNJ; j++)
#pragma unroll
            for (int r = 0; r < 4; r++) acc[i][j][r] = 0.f;

    int NC = K / 64;
    gemm_stage64<NT>(sb, A, Bw, row0, col0, K, 0, tid);            CP_COMMIT();
    gemm_stage64<NT>(sb + SSTAGE, A, Bw, row0, col0, K, 64, tid);  CP_COMMIT();

    int a_row  = wm * (WMI * 16) + (lane & 15);
    int a_koff = (lane >> 4) << 4;
    int b_row0 = wn * WNSPAN + ((lane >> 4) << 3) + (lane & 7);
    int b_koff = ((lane >> 3) & 1) << 4;

    for (int c = 0; c < NC; c++) {
        CP_WAIT1();
        __syncthreads();
        if (c + 2 < NC)
            gemm_stage64<NT>(sb + ((c + 2) % 3) * SSTAGE, A, Bw, row0, col0, K, (c + 2) * 64, tid);
        CP_COMMIT();   // unconditional: guarantees wait_group 1 covers stage c (no tail race)
        uint32_t stA = sb + (c % 3) * SSTAGE;
        uint32_t stB = stA + ABYTES;
#pragma unroll
        for (int ks = 0; ks < 4; ks++) {
            uint32_t af[WMI][4];
#pragma unroll
            for (int i = 0; i < WMI; i++) {
                uint32_t addr = stA + (a_row + i * 16) * 144 + ks * 32 + a_koff;
                asm volatile("ldmatrix.sync.aligned.m8n8.x4.shared.b16 {%0,%1,%2,%3}, [%4];"
                             : "=r"(af[i][0]), "=r"(af[i][1]), "=r"(af[i][2]), "=r"(af[i][3])
                             : "r"(addr));
            }
            uint32_t bf_[NBJJ][4];
#pragma unroll
            for (int jj = 0; jj < NBJJ; jj++) {
                uint32_t addr = stB + (b_row0 + jj * 16) * 144 + ks * 32 + b_koff;
                asm volatile("ldmatrix.sync.aligned.m8n8.x4.shared.b16 {%0,%1,%2,%3}, [%4];"
                             : "=r"(bf_[jj][0]), "=r"(bf_[jj][1]), "=r"(bf_[jj][2]), "=r"(bf_[jj][3])
                             : "r"(addr));
            }
#pragma unroll
            for (int i = 0; i < WMI; i++)
#pragma unroll
                for (int j = 0; j < WNJ; j++) {
                    asm volatile(
                        "mma.sync.aligned.m16n8k16.row.col.f32.bf16.bf16.f32 "
                        "{%0,%1,%2,%3}, {%4,%5,%6,%7}, {%8,%9}, {%0,%1,%2,%3};"
                        : "+f"(acc[i][j][0]), "+f"(acc[i][j][1]),
                          "+f"(acc[i][j][2]), "+f"(acc[i][j][3])
                        : "r"(af[i][0]), "r"(af[i][1]), "r"(af[i][2]), "r"(af[i][3]),
                          "r"(bf_[j >> 1][(j & 1) * 2]), "r"(bf_[j >> 1][(j & 1) * 2 + 1]));
                }
        }
        __syncthreads();
    }

    if (MODE == 3) {
        // fused out_proj epilogue: bias + residual + LayerNorm -> g_x + mirror
        float* Xr = (float*)Cv;   // g_x
        // 1) add bias + residual into acc
#pragma unroll
        for (int i = 0; i < WMI; i++) {
            int r0 = row0 + wm * 64 + i * 16 + grp;
#pragma unroll
            for (int j = 0; j < WNJ; j++) {
                int cg = col0 + wn * WNSPAN + j * 8 + qid * 2;
                float b0 = bias[cg], b1 = bias[cg + 1];
                float2 x0 = *(const float2*)&Xr[(size_t)r0 * DMODEL + cg];
                float2 x1 = *(const float2*)&Xr[(size_t)(r0 + 8) * DMODEL + cg];
                acc[i][j][0] += b0 + x0.x;
                acc[i][j][1] += b1 + x0.y;
                acc[i][j][2] += b0 + x1.x;
                acc[i][j][3] += b1 + x1.y;
            }
        }
        // 2) per-row partial sums (this warp's 64 cols), quad-reduced
        float2* sred = (float2*)smem;   // [128 rows][4 wn]
#pragma unroll
        for (int i = 0; i < WMI; i++) {
            float s0 = 0.f, q0 = 0.f, s1 = 0.f, q1 = 0.f;
#pragma unroll
            for (int j = 0; j < WNJ; j++) {
                s0 += acc[i][j][0] + acc[i][j][1];
                q0 += acc[i][j][0] * acc[i][j][0] + acc[i][j][1] * acc[i][j][1];
                s1 += acc[i][j][2] + acc[i][j][3];
                q1 += acc[i][j][2] * acc[i][j][2] + acc[i][j][3] * acc[i][j][3];
            }
            s0 += __shfl_xor_sync(0xFFFFFFFF, s0, 1); s0 += __shfl_xor_sync(0xFFFFFFFF, s0, 2);
            q0 += __shfl_xor_sync(0xFFFFFFFF, q0, 1); q0 += __shfl_xor_sync(0xFFFFFFFF, q0, 2);
            s1 += __shfl_xor_sync(0xFFFFFFFF, s1, 1); s1 += __shfl_xor_sync(0xFFFFFFFF, s1, 2);
            q1 += __shfl_xor_sync(0xFFFFFFFF, q1, 1); q1 += __shfl_xor_sync(0xFFFFFFFF, q1, 2);
            if (qid == 0) {
                int lr = wm * 64 + i * 16 + grp;
                sred[lr * 4 + wn]       = make_float2(s0, q0);
                sred[(lr + 8) * 4 + wn] = make_float2(s1, q1);
            }
        }
        __syncthreads();
        // 3) finalize LN per row and store
#pragma unroll
        for (int i = 0; i < WMI; i++) {
            int lr0 = wm * 64 + i * 16 + grp;
            float mu[2], rs[2];
#pragma unroll
            for (int rr = 0; rr < 2; rr++) {
                int lr = lr0 + rr * 8;
                float2 p0 = sred[lr * 4 + 0], p1 = sred[lr * 4 + 1];
                float2 p2 = sred[lr * 4 + 2], p3 = sred[lr * 4 + 3];
                float S  = p0.x + p1.x + p2.x + p3.x;
                float SS = p0.y + p1.y + p2.y + p3.y;
                float m  = S * (1.f / DMODEL);
                float v  = SS * (1.f / DMODEL) - m * m;
                mu[rr] = m;
                rs[rr] = rsqrtf(v + LN_EPS);
            }
            int r0 = row0 + lr0;
#pragma unroll
            for (int j = 0; j < WNJ; j++) {
                int cg = col0 + wn * WNSPAN + j * 8 + qid * 2;
                float g0 = gam[cg], g1 = gam[cg + 1];
                float t0 = bet[cg], t1 = bet[cg + 1];
                float o00 = (acc[i][j][0] - mu[0]) * rs[0] * g0 + t0;
                float o01 = (acc[i][j][1] - mu[0]) * rs[0] * g1 + t1;
                float o10 = (acc[i][j][2] - mu[1]) * rs[1] * g0 + t0;
                float o11 = (acc[i][j][3] - mu[1]) * rs[1] * g1 + t1;
                *(float2*)&Xr[(size_t)r0 * DMODEL + cg]       = make_float2(o00, o01);
                *(float2*)&Xr[(size_t)(r0 + 8) * DMODEL + cg] = make_float2(o10, o11);
                *(uint32_t*)&mirror[(size_t)r0 * DMODEL + cg]       = packbf(o00, o01);
                *(uint32_t*)&mirror[(size_t)(r0 + 8) * DMODEL + cg] = packbf(o10, o11);
            }
        }
        return;
    }

    // MODE 0/1/2 epilogue
#pragma unroll
    for (int i = 0; i < WMI; i++) {
        int rg0 = row0 + wm * (WMI * 16) + i * 16 + grp;
#pragma unroll
        for (int j = 0; j < WNJ; j++) {
            int cg = col0 + wn * WNSPAN + j * 8 + qid * 2;
            float b0 = bias[cg], b1 = bias[cg + 1];
            float v00 = acc[i][j][0] + b0, v01 = acc[i][j][1] + b1;
            float v10 = acc[i][j][2] + b0, v11 = acc[i][j][3] + b1;
            if (MODE == 2 && j < 2) {
                v00 = (v00 > 20.f) ? v00 : log1pf(__expf(v00));
                v01 = (v01 > 20.f) ? v01 : log1pf(__expf(v01));
                v10 = (v10 > 20.f) ? v10 : log1pf(__expf(v10));
                v11 = (v11 > 20.f) ? v11 : log1pf(__expf(v11));
            }
            if (MODE == 1) {
                __nv_bfloat16* Cb = (__nv_bfloat16*)Cv;
                *(uint32_t*)&Cb[(size_t)rg0 * N + cg]       = packbf(v00, v01);
                *(uint32_t*)&Cb[(size_t)(rg0 + 8) * N + cg] = packbf(v10, v11);
            } else {
                float* C = (float*)Cv;
                *(float2*)&C[(size_t)rg0 * N + cg]       = make_float2(v00, v01);
                *(float2*)&C[(size_t)(rg0 + 8) * N + cg] = make_float2(v10, v11);
            }
        }
    }
}

// ---------------- depthwise causal conv(4) + silu ----------------
__global__ void conv_silu_kernel(const float* __restrict__ cw,
                                 const float* __restrict__ cb, int l)
{
    int idx = blockIdx.x * blockDim.x + threadIdx.x;
    if (idx >= (TOKENS / 4) * 128) return;
    int g128 = idx & 127;
    int q    = idx >> 7;
    int t0   = q * 4;
    int b    = t0 / SEQ;
    int s0   = t0 % SEQ;
    int c    = g128 * 4;

    float4 w0 = *(const float4*)&cw[(l * DINNER + c + 0) * DCONV];
    float4 w1 = *(const float4*)&cw[(l * DINNER + c + 1) * DCONV];
    float4 w2 = *(const float4*)&cw[(l * DINNER + c + 2) * DCONV];
    float4 w3 = *(const float4*)&cw[(l * DINNER + c + 3) * DCONV];
    float wa[4][4] = {{w0.x,w0.y,w0.z,w0.w},{w1.x,w1.y,w1.z,w1.w},
                      {w2.x,w2.y,w2.z,w2.w},{w3.x,w3.y,w3.z,w3.w}};
    float bs0 = cb[l * DINNER + c + 0];
    float bs1 = cb[l * DINNER + c + 1];
    float bs2 = cb[l * DINNER + c + 2];
    float bs3 = cb[l * DINNER + c + 3];

    float rowv[7][4];
#pragma unroll
    for (int k = 0; k < 7; k++) {
        int s = s0 - 3 + k;
        if (s >= 0) {
            uint2 v = *(const uint2*)&g_xz[(size_t)(b * SEQ + s) * 2 * DINNER + c];
            float2 p0 = __bfloat1622float2(*(__nv_bfloat162*)&v.x);
            float2 p1 = __bfloat1622float2(*(__nv_bfloat162*)&v.y);
            rowv[k][0] = p0.x; rowv[k][1] = p0.y; rowv[k][2] = p1.x; rowv[k][3] = p1.y;
        } else {
            rowv[k][0] = rowv[k][1] = rowv[k][2] = rowv[k][3] = 0.f;
        }
    }
#pragma unroll
    for (int t = 0; t < 4; t++) {
        float o0 = bs0, o1 = bs1, o2 = bs2, o3 = bs3;
#pragma unroll
        for (int k = 0; k < DCONV; k++) {
            o0 += rowv[t + k][0] * wa[0][k];
            o1 += rowv[t + k][1] * wa[1][k];
            o2 += rowv[t + k][2] * wa[2][k];
            o3 += rowv[t + k][3] * wa[3][k];
        }
        o0 = o0 * (1.f / (1.f + __expf(-o0)));
        o1 = o1 * (1.f / (1.f + __expf(-o1)));
        o2 = o2 * (1.f / (1.f + __expf(-o2)));
        o3 = o3 * (1.f / (1.f + __expf(-o3)));
        *(uint2*)&g_xs[(size_t)(b * SEQ + s0 + t) * DINNER + c] =
            make_uint2(packbf(o0, o1), packbf(o2, o3));
    }
}

// ---------------- selective scan: cp.async chunked SMEM pipeline ----------------
#define SCH 18
#define SST 11520

__device__ __forceinline__ void scan_stage(uint32_t dst, int b, int d0, int t0, int tid)
{
    const char* ssrc = (const char*)(g_ssm + (size_t)(b * SEQ + t0) * 32);
#pragma unroll 2
    for (int i = tid; i < 144; i += 128)
        CP_ASYNC16(dst + i * 16, ssrc + i * 16);
#pragma unroll 3
    for (int i = tid; i < 288; i += 128) {
        int r = i >> 4, o = (i & 15) << 4;
        CP_ASYNC16(dst + 2304 + r * 256 + o,
                   (const char*)(g_xs + (size_t)(b * SEQ + t0 + r) * DINNER + d0) + o);
    }
#pragma unroll 3
    for (int i = tid; i < 288; i += 128) {
        int r = i >> 4, o = (i & 15) << 4;
        CP_ASYNC16(dst + 6912 + r * 256 + o,
                   (const char*)(g_xz + (size_t)(b * SEQ + t0 + r) * 2 * DINNER + DINNER + d0) + o);
    }
}

__global__ __launch_bounds__(128) void scan_kernel(const float* __restrict__ A_log,
                                                   const float* __restrict__ Dp, int l)
{
    extern __shared__ char ssm_smem[];
    uint32_t sb = smem_u32(ssm_smem);
    int tid = threadIdx.x;
    int b   = blockIdx.x;
    int d0  = blockIdx.y * 128;
    int d   = d0 + tid;

    const float* Al = A_log + (size_t)(l * DINNER + d) * DSTATE;
    float a2[DSTATE];
#pragma unroll
    for (int n = 0; n < DSTATE; n++) a2[n] = -__expf(Al[n]) * LOG2E;
    float Dv = Dp[l * DINNER + d];
    float h[DSTATE];
#pragma unroll
    for (int n = 0; n < DSTATE; n++) h[n] = 0.f;

    scan_stage(sb, b, d0, 0, tid);           CP_COMMIT();
    scan_stage(sb + SST, b, d0, SCH, tid);   CP_COMMIT();

    int tok0 = b * SEQ;
    for (int c = 0; c < 50; c++) {
        CP_WAIT1();
        __syncthreads();
        int st = (c & 1);
        const float* ssp = (const float*)(ssm_smem + st * SST);
        const __nv_bfloat16* xsp = (const __nv_bfloat16*)(ssm_smem + st * SST + 2304);
        const __nv_bfloat16* rsp = (const __nv_bfloat16*)(ssm_smem + st * SST + 6912);
        __nv_bfloat16* yp = g_yb + (size_t)(tok0 + c * SCH) * DINNER + d;

#pragma unroll 2
        for (int t = 0; t < SCH; t++) {
            const float4* sp = (const float4*)(ssp + t * 32);
            float4 d0v = sp[0], d1v = sp[1], d2v = sp[2], d3v = sp[3];
            float4 b0v = sp[4], b1v = sp[5], b2v = sp[6], b3v = sp[7];
            float dl[DSTATE] = {d0v.x,d0v.y,d0v.z,d0v.w, d1v.x,d1v.y,d1v.z,d1v.w,
                                d2v.x,d2v.y,d2v.z,d2v.w, d3v.x,d3v.y,d3v.z,d3v.w};
            float bm[DSTATE] = {b0v.x,b0v.y,b0v.z,b0v.w, b1v.x,b1v.y,b1v.z,b1v.w,
                                b2v.x,b2v.y,b2v.z,b2v.w, b3v.x,b3v.y,b3v.z,b3v.w};
            float xv = __bfloat162float(xsp[t * 128 + tid]);
            float rv = __bfloat162float(rsp[t * 128 + tid]);
            float accv = 0.f;
#pragma unroll
            for (int n = 0; n < DSTATE; n++) {
                float e = exp2f(a2[n] * dl[n]);
                h[n] = h[n] * e + xv * bm[n];
                accv += h[n] * bm[n];
            }
            float sl = rv * (1.f / (1.f + __expf(-rv)));
            yp[(size_t)t * DINNER] = __float2bfloat16((accv + Dv * xv) * sl);
        }
        __syncthreads();
        if (c + 2 < 50)
            scan_stage(sb + st * SST, b, d0, (c + 2) * SCH, tid);
        CP_COMMIT();   // unconditional: no tail race on last chunks
    }
}

// ---------------- heads ----------------
__global__ void heads_kernel(const float* __restrict__ c1w, const float* __restrict__ c1b,
                             const float* __restrict__ c2w, const float* __restrict__ c2b,
                             const float* __restrict__ q1w, const float* __restrict__ q1b,
                             const float* __restrict__ q2w, const float* __restrict__ q2b,
                             float* __restrict__ out)
{
    __shared__ float fin[DMODEL];
    __shared__ float hc[128], hq[128];
    int b = blockIdx.x, t = threadIdx.x;
    const float* f = g_x + (size_t)(b * SEQ + SEQ - 1) * DMODEL;
    fin[t] = f[t];
    fin[t + 128] = f[t + 128];
    __syncthreads();
    float a1 = c1b[t], a2 = q1b[t];
#pragma unroll 4
    for (int k = 0; k < DMODEL; k++) {
        float fv = fin[k];
        a1 += fv * c1w[k * 128 + t];
        a2 += fv * q1w[k * 128 + t];
    }
    hc[t] = fmaxf(a1, 0.f);
    hq[t] = fmaxf(a2, 0.f);
    __syncthreads();
    if (t == 0) {
        float s = c2b[0];
        for (int k = 0; k < 128; k++) s += hc[k] * c2w[k];
        out[b] = fmaxf(s, 0.f);
    }
    if (t < 10) {
        float s = q2b[t];
        for (int k = 0; k < 128; k++) s += hq[k] * q2w[k * 10 + t];
        out[BATCH + b * 10 + t] = fmaxf(s, 0.f);
    }
}

// ---------------- launch ----------------
extern "C" void kernel_launch(void* const* d_in, const int* in_sizes, int n_in,
                              void* d_out, int out_size)
{
    const int*   grid   = (const int*)  d_in[0];
    const float* ce     = (const float*)d_in[1];
    const float* pe     = (const float*)d_in[2];
    const float* in_w   = (const float*)d_in[3];
    const float* in_b   = (const float*)d_in[4];
    const float* conv_w = (const float*)d_in[5];
    const float* conv_b = (const float*)d_in[6];
    const float* xp_w   = (const float*)d_in[7];
    const float* xp_b   = (const float*)d_in[8];
    const float* A_log  = (const float*)d_in[9];
    const float* Dp     = (const float*)d_in[10];
    const float* out_w  = (const float*)d_in[11];
    const float* out_b  = (const float*)d_in[12];
    const float* ln_g   = (const float*)d_in[13];
    const float* ln_b   = (const float*)d_in[14];
    const float* c1w    = (const float*)d_in[15];
    const float* c1b    = (const float*)d_in[16];
    const float* c2w    = (const float*)d_in[17];
    const float* c2b    = (const float*)d_in[18];
    const float* q1w    = (const float*)d_in[19];
    const float* q1b    = (const float*)d_in[20];
    const float* q2w    = (const float*)d_in[21];
    const float* q2b    = (const float*)d_in[22];
    float* out = (float*)d_out;

    __nv_bfloat16 *pxb, *pyb, *pxz, *pxs;
    uint32_t *pwbi, *pwbo, *pwbx;
    float *px, *pssm;
    cudaGetSymbolAddress((void**)&px,   g_x);
    cudaGetSymbolAddress((void**)&pxb,  g_xb);
    cudaGetSymbolAddress((void**)&pyb,  g_yb);
    cudaGetSymbolAddress((void**)&pxz,  g_xz);
    cudaGetSymbolAddress((void**)&pxs,  g_xs);
    cudaGetSymbolAddress((void**)&pssm, g_ssm);
    cudaGetSymbolAddress((void**)&pwbi, g_wbi);
    cudaGetSymbolAddress((void**)&pwbo, g_wbo);
    cudaGetSymbolAddress((void**)&pwbx, g_wbx);

    const int SM128 = 3 * (128 + 128) * 144;   // 110592
    const int SM256 = 3 * (128 + 256) * 144;   // 165888
    const int SM32  = 3 * (128 + 32) * 144;    // 69120
    cudaFuncSetAttribute(gemm_bf16_kernel<128, 1>, cudaFuncAttributeMaxDynamicSharedMemorySize, SM128);
    cudaFuncSetAttribute(gemm_bf16_kernel<256, 3>, cudaFuncAttributeMaxDynamicSharedMemorySize, SM256);
    cudaFuncSetAttribute(gemm_bf16_kernel<32, 2>,  cudaFuncAttributeMaxDynamicSharedMemorySize, SM32);

    {
        int nA = NLAYERS * 2 * DINNER * (DMODEL / 2);
        convert_in_w_kernel<<<(nA + 255) / 256, 256>>>(in_w, pwbi);
        int nB = NLAYERS * DMODEL * (DINNER / 2);
        convert_out_w_kernel<<<(nB + 255) / 256, 256>>>(out_w, pwbo);
        int nX = NLAYERS * 32 * (DINNER / 2);
        convert_xp_w_kernel<<<(nX + 255) / 256, 256>>>(xp_w, pwbx);
        int n = TOKENS * (DMODEL / 4);
        embed_kernel<<<(n + 255) / 256, 256>>>(grid, ce, pe);
    }

    for (int l = 0; l < NLAYERS; l++) {
        // in_proj: (T x 256) -> 1024, bf16 out
        gemm_bf16_kernel<128, 1><<<dim3(8, TOKENS / 128), 256, SM128>>>(
            pxb, (const __nv_bfloat16*)(pwbi + (size_t)l * 2 * DINNER * (DMODEL / 2)),
            in_b + l * 2 * DINNER, pxz, TOKENS, 2 * DINNER, DMODEL,
            nullptr, nullptr, nullptr);

        {
            int n = (TOKENS / 4) * 128;
            conv_silu_kernel<<<(n + 255) / 256, 256>>>(conv_w, conv_b, l);
        }

        // xproj: (T x 512) -> 32, softplus fused
        gemm_bf16_kernel<32, 2><<<dim3(1, TOKENS / 128), 256, SM32>>>(
            pxs, (const __nv_bfloat16*)(pwbx + (size_t)l * 32 * (DINNER / 2)),
            xp_b + l * 32, pssm, TOKENS, 32, DINNER,
            nullptr, nullptr, nullptr);

        scan_kernel<<<dim3(BATCH, DINNER / 128), 128, 2 * SST>>>(A_log, Dp, l);

        // out_proj fused: (T x 512) -> 256 + bias + residual + LN -> g_x / g_xb
        gemm_bf16_kernel<256, 3><<<dim3(1, TOKENS / 128), 256, SM256>>>(
            pyb, (const __nv_bfloat16*)(pwbo + (size_t)l * DMODEL * (DINNER / 2)),
            out_b + l * DMODEL, px, TOKENS, DMODEL, DINNER,
            ln_g, ln_b, pxb);
    }

    heads_kernel<<<BATCH, 128>>>(c1w, c1b, c2w, c2b, q1w, q1b, q2w, q2b, out);
}